// round 1
// baseline (speedup 1.0000x reference)
#include <cuda_runtime.h>

// ============================================================================
// FullGap: out[s] = sum_{i in s} (p_i^T M p_i) / (p_i . p_i)
//          M      = sum_j weights[colseg[j]] * s_j s_j^T     (256 x 256)
// Three launches: zero -> build M (split-K atomic GEMM) -> fused quad-form.
// All fp32, packed fma.rn.f32x2 inner loops.
// ============================================================================

#define D_FEAT 256
#define KC 16
#define MT 64        // M-kernel tile dim (64x64 tiles of the 256x256 output)
#define NSPLIT 16    // split-K factor for building M
#define QROWS 64     // atoms per block in quad kernel

__device__ float g_M[D_FEAT * D_FEAT];

// ---- packed f32x2 helpers -------------------------------------------------
__device__ __forceinline__ unsigned long long pk2(float lo, float hi) {
    unsigned long long r;
    asm("mov.b64 %0, {%1,%2};" : "=l"(r) : "f"(lo), "f"(hi));
    return r;
}
__device__ __forceinline__ float2 up2(unsigned long long v) {
    float2 f;
    asm("mov.b64 {%0,%1}, %2;" : "=f"(f.x), "=f"(f.y) : "l"(v));
    return f;
}
__device__ __forceinline__ void ffma2(unsigned long long& d,
                                      unsigned long long a,
                                      unsigned long long b) {
    asm("fma.rn.f32x2 %0, %1, %2, %3;" : "=l"(d) : "l"(a), "l"(b), "l"(d));
}

// ---- kernel 0: zero scratch + output --------------------------------------
__global__ void k_zero(float* __restrict__ out, int n_struct) {
    int i = blockIdx.x * blockDim.x + threadIdx.x;
    if (i < D_FEAT * D_FEAT) g_M[i] = 0.0f;
    if (i < n_struct) out[i] = 0.0f;
}

// ---- kernel 1: M = S^T diag(w) S, split-K with atomic accumulate ----------
__global__ void __launch_bounds__(256)
k_build_M(const float* __restrict__ S, const float* __restrict__ W,
          const int* __restrict__ colseg, int n_support) {
    __shared__ __align__(16) float sa[KC][MT];
    __shared__ __align__(16) float sb[KC][MT];

    const int tile  = blockIdx.x;            // 0..15 -> (a-tile, b-tile)
    const int split = blockIdx.y;            // 0..NSPLIT-1
    const int a0 = (tile & 3) * MT;
    const int b0 = (tile >> 2) * MT;
    const int span   = (n_support + NSPLIT - 1) / NSPLIT;
    const int jstart = split * span;
    const int jend   = min(jstart + span, n_support);

    const int t  = threadIdx.x;
    const int tx = t & 15;                   // 16 col-groups of 4
    const int ty = t >> 4;                   // 16 row-groups of 4

    unsigned long long acc[4][2];
#pragma unroll
    for (int r = 0; r < 4; r++) { acc[r][0] = pk2(0.f, 0.f); acc[r][1] = pk2(0.f, 0.f); }

    for (int j0 = jstart; j0 < jend; j0 += KC) {
#pragma unroll
        for (int e = 0; e < 4; e++) {
            int kk  = (t >> 6) + 4 * e;      // 0..15
            int col = t & 63;
            int j = j0 + kk;
            float va = 0.f, vb = 0.f;
            if (j < jend) {
                va = S[(size_t)j * D_FEAT + a0 + col];
                float w = W[colseg[j]];
                vb = S[(size_t)j * D_FEAT + b0 + col] * w;
            }
            sa[kk][col] = va;
            sb[kk][col] = vb;
        }
        __syncthreads();
#pragma unroll
        for (int kk = 0; kk < KC; kk++) {
            float4 av = *(const float4*)&sa[kk][ty * 4];
            float4 bv = *(const float4*)&sb[kk][tx * 4];
            unsigned long long b01 = pk2(bv.x, bv.y);
            unsigned long long b23 = pk2(bv.z, bv.w);
            float ar[4] = {av.x, av.y, av.z, av.w};
#pragma unroll
            for (int r = 0; r < 4; r++) {
                unsigned long long a2 = pk2(ar[r], ar[r]);
                ffma2(acc[r][0], a2, b01);
                ffma2(acc[r][1], a2, b23);
            }
        }
        __syncthreads();
    }

#pragma unroll
    for (int r = 0; r < 4; r++) {
        float2 c01 = up2(acc[r][0]);
        float2 c23 = up2(acc[r][1]);
        int row = a0 + ty * 4 + r;
        float* mrow = &g_M[(size_t)row * D_FEAT + b0 + tx * 4];
        atomicAdd(mrow + 0, c01.x);
        atomicAdd(mrow + 1, c01.y);
        atomicAdd(mrow + 2, c23.x);
        atomicAdd(mrow + 3, c23.y);
    }
}

// ---- kernel 2: q_i = (p_i^T M p_i)/(p_i.p_i), atomicAdd into out[seg] -----
// Block = 256 threads = 8 warps (ty=warp) x 32 lanes (tx).
// Block tile: QROWS=64 atom rows x all 256 columns of Y = X @ M.
// Thread: 8 rows (ty*8..) x 8 cols (tx*8..), accumulators packed over row-pairs.
__global__ void __launch_bounds__(256)
k_quad(const float* __restrict__ X, const int* __restrict__ rowseg,
       float* __restrict__ out, int n_atoms) {
    __shared__ __align__(16) float xa[KC][QROWS + 2];   // k-major X chunk (stride 66)
    __shared__ __align__(16) float mb[KC][D_FEAT];      // M chunk

    const int row0 = blockIdx.x * QROWS;
    const int t  = threadIdx.x;
    const int tx = t & 31;
    const int ty = t >> 5;

    // acc[r2][c] = packed {Y[2*r2], Y[2*r2+1]} for column tx*8+c
    unsigned long long acc[4][8];
#pragma unroll
    for (int r2 = 0; r2 < 4; r2++)
#pragma unroll
        for (int c = 0; c < 8; c++) acc[r2][c] = pk2(0.f, 0.f);

    for (int k0 = 0; k0 < D_FEAT; k0 += KC) {
        // X chunk: 64 rows x 16 k  (1024 elems, 4 per thread)
#pragma unroll
        for (int e = 0; e < 4; e++) {
            int kk  = t & 15;
            int row = (t >> 4) + 16 * e;
            float v = 0.f;
            if (row0 + row < n_atoms)
                v = X[(size_t)(row0 + row) * D_FEAT + k0 + kk];
            xa[kk][row] = v;
        }
        // M chunk: 16 x 256 (4096 elems, 16 per thread, fully coalesced)
#pragma unroll
        for (int e = 0; e < KC; e++)
            mb[e][t] = g_M[(size_t)(k0 + e) * D_FEAT + t];
        __syncthreads();

#pragma unroll
        for (int kk = 0; kk < KC; kk++) {
            // a: packed row-pairs straight from smem (contiguous rows)
            unsigned long long a2[4];
#pragma unroll
            for (int r2 = 0; r2 < 4; r2++)
                a2[r2] = *(const unsigned long long*)&xa[kk][ty * 8 + 2 * r2];
            float4 bv0 = *(const float4*)&mb[kk][tx * 8];
            float4 bv1 = *(const float4*)&mb[kk][tx * 8 + 4];
            float bs[8] = {bv0.x, bv0.y, bv0.z, bv0.w, bv1.x, bv1.y, bv1.z, bv1.w};
#pragma unroll
            for (int c = 0; c < 8; c++) {
                unsigned long long bd = pk2(bs[c], bs[c]);
#pragma unroll
                for (int r2 = 0; r2 < 4; r2++) ffma2(acc[r2][c], a2[r2], bd);
            }
        }
        __syncthreads();
    }

    // Epilogue: q[r] = sum_c x*y, n[r] = sum_c x*x, reduce across lanes.
    float yv[8][8];
#pragma unroll
    for (int r2 = 0; r2 < 4; r2++)
#pragma unroll
        for (int c = 0; c < 8; c++) {
            float2 y2 = up2(acc[r2][c]);
            yv[2 * r2][c]     = y2.x;
            yv[2 * r2 + 1][c] = y2.y;
        }

#pragma unroll
    for (int r = 0; r < 8; r++) {
        int row = row0 + ty * 8 + r;
        float q = 0.f, nn = 0.f;
        if (row < n_atoms) {
            const float4* xp = (const float4*)&X[(size_t)row * D_FEAT + tx * 8];
            float4 x0 = xp[0];
            float4 x1 = xp[1];
            float xs[8] = {x0.x, x0.y, x0.z, x0.w, x1.x, x1.y, x1.z, x1.w};
#pragma unroll
            for (int c = 0; c < 8; c++) {
                q  = fmaf(xs[c], yv[r][c], q);
                nn = fmaf(xs[c], xs[c], nn);
            }
        }
#pragma unroll
        for (int off = 16; off > 0; off >>= 1) {
            q  += __shfl_down_sync(0xFFFFFFFFu, q, off);
            nn += __shfl_down_sync(0xFFFFFFFFu, nn, off);
        }
        if (tx == 0 && row < n_atoms) {
            atomicAdd(&out[rowseg[row]], q / nn);
        }
    }
}

// ---- launch ----------------------------------------------------------------
extern "C" void kernel_launch(void* const* d_in, const int* in_sizes, int n_in,
                              void* d_out, int out_size) {
    const float* X      = (const float*)d_in[0];  // power_spectrum [n_atoms, 256]
    const float* S      = (const float*)d_in[1];  // support        [n_support, 256]
    const float* W      = (const float*)d_in[2];  // weights        [n_train]
    const int*   rowseg = (const int*)d_in[3];    // [n_atoms]
    const int*   colseg = (const int*)d_in[4];    // [n_support]
    float* out = (float*)d_out;

    int n_atoms   = in_sizes[0] / D_FEAT;
    int n_support = in_sizes[1] / D_FEAT;
    int n_struct  = out_size;

    k_zero<<<(D_FEAT * D_FEAT + 255) / 256, 256>>>(out, n_struct);

    dim3 gM(16, NSPLIT);
    k_build_M<<<gM, 256>>>(S, W, colseg, n_support);

    int gQ = (n_atoms + QROWS - 1) / QROWS;
    k_quad<<<gQ, 256>>>(X, rowseg, out, n_atoms);
}

// round 3
// speedup vs baseline: 1.4679x; 1.4679x over previous
#include <cuda_runtime.h>
#include <cuda_bf16.h>
#include <cstdint>

// ============================================================================
// FullGap: out[s] = sum_{i in s} (p_i^T M p_i) / (p_i . p_i)
//          M      = sum_j weights[colseg[j]] * s_j s_j^T   (256x256)
// Pipeline: zero -> build M (fp32 split-K) -> M -> bf16 hi/lo ->
//           HMMA quad-form kernel (mma.sync m16n8k16 bf16, 3-split, fp32 acc).
// NOTE: harness compiles PTX at target sm_103 (no 'a') -> tcgen05 unavailable;
//       warp-level mma.sync is the tensor path that works.
// ============================================================================

#define D_FEAT 256
#define KC 16
#define MT 64
#define NSPLIT 16
#define QM 128          // atom rows per HMMA CTA

__device__ float g_M[D_FEAT * D_FEAT];
__device__ __align__(16) __nv_bfloat16 g_Mhi[D_FEAT * D_FEAT];
__device__ __align__(16) __nv_bfloat16 g_Mlo[D_FEAT * D_FEAT];

// ---------------- helpers ----------------------------------------------------
__device__ __forceinline__ uint32_t smem_u32(const void* p) {
    uint32_t a;
    asm("{ .reg .u64 t; cvta.to.shared.u64 t, %1; cvt.u32.u64 %0, t; }"
        : "=r"(a) : "l"(p));
    return a;
}
__device__ __forceinline__ uint32_t sw_off(uint32_t off) {   // SW128 swizzle
    return off ^ ((off >> 3) & 0x70);
}
__device__ __forceinline__ unsigned long long pk2(float lo, float hi) {
    unsigned long long r;
    asm("mov.b64 %0, {%1,%2};" : "=l"(r) : "f"(lo), "f"(hi));
    return r;
}
__device__ __forceinline__ float2 up2(unsigned long long v) {
    float2 f;
    asm("mov.b64 {%0,%1}, %2;" : "=f"(f.x), "=f"(f.y) : "l"(v));
    return f;
}
__device__ __forceinline__ void ffma2(unsigned long long& d,
                                      unsigned long long a,
                                      unsigned long long b) {
    asm("fma.rn.f32x2 %0, %1, %2, %3;" : "=l"(d) : "l"(a), "l"(b), "l"(d));
}

// ldmatrix x4: A tile fragment (rows rb..rb+15, k kk..kk+15), SW128 smem
__device__ __forceinline__ void ldsmA(uint32_t base, int rb, int kk, int lane,
                                      uint32_t* a) {
    int g = lane >> 3, r = lane & 7;
    int row = rb + r + (g & 1) * 8;
    int col = kk + (g >> 1) * 8;
    uint32_t addr = base + sw_off((uint32_t)(row * 128 + col * 2));
    asm volatile("ldmatrix.sync.aligned.m8n8.x4.shared.b16 {%0,%1,%2,%3}, [%4];"
                 : "=r"(a[0]), "=r"(a[1]), "=r"(a[2]), "=r"(a[3]) : "r"(addr));
}
// ldmatrix x4: B fragments for 2 n8-tiles (n nb..nb+15, k kk..kk+15)
__device__ __forceinline__ void ldsmB(uint32_t base, int nb, int kk, int lane,
                                      uint32_t* b) {
    int g = lane >> 3, r = lane & 7;
    int row = nb + r + (g >> 1) * 8;
    int col = kk + (g & 1) * 8;
    uint32_t addr = base + sw_off((uint32_t)(row * 128 + col * 2));
    asm volatile("ldmatrix.sync.aligned.m8n8.x4.shared.b16 {%0,%1,%2,%3}, [%4];"
                 : "=r"(b[0]), "=r"(b[1]), "=r"(b[2]), "=r"(b[3]) : "r"(addr));
}
__device__ __forceinline__ void mma16816(float* c, const uint32_t* a,
                                         const uint32_t* b) {
    asm volatile(
        "mma.sync.aligned.m16n8k16.row.col.f32.bf16.bf16.f32 "
        "{%0,%1,%2,%3}, {%4,%5,%6,%7}, {%8,%9}, {%0,%1,%2,%3};"
        : "+f"(c[0]), "+f"(c[1]), "+f"(c[2]), "+f"(c[3])
        : "r"(a[0]), "r"(a[1]), "r"(a[2]), "r"(a[3]), "r"(b[0]), "r"(b[1]));
}

// ---- kernel 0: zero scratch + output ----------------------------------------
__global__ void k_zero(float* __restrict__ out, int n_struct) {
    int i = blockIdx.x * blockDim.x + threadIdx.x;
    if (i < D_FEAT * D_FEAT) g_M[i] = 0.0f;
    if (i < n_struct) out[i] = 0.0f;
}

// ---- kernel 1: M = S^T diag(w) S (fp32, split-K, atomic) ---------------------
__global__ void __launch_bounds__(256)
k_build_M(const float* __restrict__ S, const float* __restrict__ W,
          const int* __restrict__ colseg, int n_support) {
    __shared__ __align__(16) float sa[KC][MT];
    __shared__ __align__(16) float sb[KC][MT];

    const int tile  = blockIdx.x;
    const int split = blockIdx.y;
    const int a0 = (tile & 3) * MT;
    const int b0 = (tile >> 2) * MT;
    const int span   = (n_support + NSPLIT - 1) / NSPLIT;
    const int jstart = split * span;
    const int jend   = min(jstart + span, n_support);

    const int t  = threadIdx.x;
    const int tx = t & 15;
    const int ty = t >> 4;

    unsigned long long acc[4][2];
#pragma unroll
    for (int r = 0; r < 4; r++) { acc[r][0] = pk2(0.f, 0.f); acc[r][1] = pk2(0.f, 0.f); }

    for (int j0 = jstart; j0 < jend; j0 += KC) {
#pragma unroll
        for (int e = 0; e < 4; e++) {
            int kk  = (t >> 6) + 4 * e;
            int col = t & 63;
            int j = j0 + kk;
            float va = 0.f, vb = 0.f;
            if (j < jend) {
                va = S[(size_t)j * D_FEAT + a0 + col];
                float w = W[colseg[j]];
                vb = S[(size_t)j * D_FEAT + b0 + col] * w;
            }
            sa[kk][col] = va;
            sb[kk][col] = vb;
        }
        __syncthreads();
#pragma unroll
        for (int kk = 0; kk < KC; kk++) {
            float4 av = *(const float4*)&sa[kk][ty * 4];
            float4 bv = *(const float4*)&sb[kk][tx * 4];
            unsigned long long b01 = pk2(bv.x, bv.y);
            unsigned long long b23 = pk2(bv.z, bv.w);
            float ar[4] = {av.x, av.y, av.z, av.w};
#pragma unroll
            for (int r = 0; r < 4; r++) {
                unsigned long long a2 = pk2(ar[r], ar[r]);
                ffma2(acc[r][0], a2, b01);
                ffma2(acc[r][1], a2, b23);
            }
        }
        __syncthreads();
    }

#pragma unroll
    for (int r = 0; r < 4; r++) {
        float2 c01 = up2(acc[r][0]);
        float2 c23 = up2(acc[r][1]);
        int row = a0 + ty * 4 + r;
        float* mrow = &g_M[(size_t)row * D_FEAT + b0 + tx * 4];
        atomicAdd(mrow + 0, c01.x);
        atomicAdd(mrow + 1, c01.y);
        atomicAdd(mrow + 2, c23.x);
        atomicAdd(mrow + 3, c23.y);
    }
}

// ---- kernel 2: M -> bf16 hi/lo split -----------------------------------------
__global__ void k_convM() {
    int i = blockIdx.x * blockDim.x + threadIdx.x;
    float v = g_M[i];
    __nv_bfloat16 h = __float2bfloat16(v);
    g_Mhi[i] = h;
    g_Mlo[i] = __float2bfloat16(v - __bfloat162float(h));
}

// ---- kernel 3: HMMA quad-form -------------------------------------------------
// CTA: 512 thr (16 warps, 4 row x 4 col). Tile 128 rows x 256 cols, K in 4x64.
// SMEM: Ahi 16K | Alo 16K | Bhi 32K | Blo 32K | qrow 512B
#define SM2_AHI 0
#define SM2_ALO 16384
#define SM2_BHI 32768
#define SM2_BLO 65536
#define SM2_Q   98304
#define SM2_TOTAL 98944

__global__ void __launch_bounds__(512, 1)
k_quad_mma(const float* __restrict__ X, const int* __restrict__ rowseg,
           float* __restrict__ out, int n_atoms) {
    extern __shared__ char smem[];
    float* qrow = (float*)(smem + SM2_Q);
    const uint32_t sbase = smem_u32(smem);
    const int t    = threadIdx.x;
    const int lane = t & 31;
    const int w    = t >> 5;
    const int wr   = w >> 2;      // warp row group (0..3) -> rows wr*32..+32
    const int wc   = w & 3;       // warp col group (0..3) -> cols wc*64..+64
    const int row0 = blockIdx.x * QM;

    if (t < QM) qrow[t] = 0.f;

    float acc[2][8][4];
#pragma unroll
    for (int mt = 0; mt < 2; mt++)
#pragma unroll
        for (int nt = 0; nt < 8; nt++)
#pragma unroll
            for (int e = 0; e < 4; e++) acc[mt][nt][e] = 0.f;

#pragma unroll 1
    for (int c = 0; c < 4; c++) {
        const int k0 = c * 64;
        if (c) __syncthreads();

        // ---- A: X fp32 -> bf16 hi/lo, SW128 smem (128 rows x 64 k) ----
#pragma unroll
        for (int p = 0; p < 4; p++) {
            int g   = t + p * 512;     // float4 granules, 2048 total
            int row = g >> 4;
            int kq  = g & 15;
            float4 v = make_float4(0.f, 0.f, 0.f, 0.f);
            if (row0 + row < n_atoms)
                v = *(const float4*)&X[(size_t)(row0 + row) * D_FEAT + k0 + kq * 4];
            float h0 = __bfloat162float(__float2bfloat16(v.x));
            float h1 = __bfloat162float(__float2bfloat16(v.y));
            float h2 = __bfloat162float(__float2bfloat16(v.z));
            float h3 = __bfloat162float(__float2bfloat16(v.w));
            __nv_bfloat162 hA = __floats2bfloat162_rn(h0, h1);
            __nv_bfloat162 hB = __floats2bfloat162_rn(h2, h3);
            __nv_bfloat162 lA = __floats2bfloat162_rn(v.x - h0, v.y - h1);
            __nv_bfloat162 lB = __floats2bfloat162_rn(v.z - h2, v.w - h3);
            uint32_t so = sw_off((uint32_t)(row * 128 + kq * 8));
            *(uint2*)(smem + SM2_AHI + so) = make_uint2(*(uint32_t*)&hA, *(uint32_t*)&hB);
            *(uint2*)(smem + SM2_ALO + so) = make_uint2(*(uint32_t*)&lA, *(uint32_t*)&lB);
        }
        // ---- B: M hi/lo chunk [256 n x 64 k], SW128 smem ----
#pragma unroll
        for (int p = 0; p < 4; p++) {
            int g   = t + p * 512;     // 16B granules, 2048 total
            int row = g >> 3;
            int kq  = g & 7;
            uint4 vh = *(const uint4*)&g_Mhi[row * D_FEAT + k0 + kq * 8];
            uint4 vl = *(const uint4*)&g_Mlo[row * D_FEAT + k0 + kq * 8];
            uint32_t so = sw_off((uint32_t)(row * 128 + kq * 16));
            *(uint4*)(smem + SM2_BHI + so) = vh;
            *(uint4*)(smem + SM2_BLO + so) = vl;
        }
        __syncthreads();

        // ---- compute: 4 k-steps of 16 ----
#pragma unroll
        for (int ks = 0; ks < 4; ks++) {
            const int kk = ks * 16;
            uint32_t Ah[2][4], Al[2][4];
            ldsmA(sbase + SM2_AHI, wr * 32 + 0,  kk, lane, Ah[0]);
            ldsmA(sbase + SM2_AHI, wr * 32 + 16, kk, lane, Ah[1]);
            ldsmA(sbase + SM2_ALO, wr * 32 + 0,  kk, lane, Al[0]);
            ldsmA(sbase + SM2_ALO, wr * 32 + 16, kk, lane, Al[1]);
#pragma unroll
            for (int np = 0; np < 4; np++) {
                uint32_t Bh[4], Bl[4];
                ldsmB(sbase + SM2_BHI, wc * 64 + np * 16, kk, lane, Bh);
                ldsmB(sbase + SM2_BLO, wc * 64 + np * 16, kk, lane, Bl);
#pragma unroll
                for (int mt = 0; mt < 2; mt++) {
#pragma unroll
                    for (int n2 = 0; n2 < 2; n2++) {
                        float* C = acc[mt][np * 2 + n2];
                        mma16816(C, Ah[mt], Bh + n2 * 2);
                        mma16816(C, Ah[mt], Bl + n2 * 2);
                        mma16816(C, Al[mt], Bh + n2 * 2);
                    }
                }
            }
        }
    }

    // ---- epilogue: q partials from register fragments -> qrow ----
#pragma unroll
    for (int mt = 0; mt < 2; mt++) {
#pragma unroll
        for (int half = 0; half < 2; half++) {
            int rloc = wr * 32 + mt * 16 + (lane >> 2) + half * 8;
            int rg   = row0 + rloc;
            float qp = 0.f;
            if (rg < n_atoms) {
#pragma unroll
                for (int nt = 0; nt < 8; nt++) {
                    int col = wc * 64 + nt * 8 + (lane & 3) * 2;
                    float2 xv = *(const float2*)&X[(size_t)rg * D_FEAT + col];
                    qp = fmaf(xv.x, acc[mt][nt][half * 2 + 0], qp);
                    qp = fmaf(xv.y, acc[mt][nt][half * 2 + 1], qp);
                }
            }
            qp += __shfl_xor_sync(0xFFFFFFFFu, qp, 1);
            qp += __shfl_xor_sync(0xFFFFFFFFu, qp, 2);
            if ((lane & 3) == 0) atomicAdd(&qrow[rloc], qp);
        }
    }
    __syncthreads();

    // ---- pass 2: per-row norm + output atomic (warp w -> rows w*8..w*8+8) ----
#pragma unroll
    for (int i = 0; i < 8; i++) {
        int rloc = w * 8 + i;
        int rg   = row0 + rloc;
        if (rg >= n_atoms) continue;
        const float4* xp = (const float4*)&X[(size_t)rg * D_FEAT + lane * 8];
        float4 x0 = xp[0];
        float4 x1 = xp[1];
        float nn = x0.x * x0.x + x0.y * x0.y + x0.z * x0.z + x0.w * x0.w +
                   x1.x * x1.x + x1.y * x1.y + x1.z * x1.z + x1.w * x1.w;
#pragma unroll
        for (int off = 16; off > 0; off >>= 1)
            nn += __shfl_xor_sync(0xFFFFFFFFu, nn, off);
        if (lane == 0) atomicAdd(&out[rowseg[rg]], qrow[rloc] / nn);
    }
}

// ---- launch -------------------------------------------------------------------
extern "C" void kernel_launch(void* const* d_in, const int* in_sizes, int n_in,
                              void* d_out, int out_size) {
    const float* X      = (const float*)d_in[0];
    const float* S      = (const float*)d_in[1];
    const float* W      = (const float*)d_in[2];
    const int*   rowseg = (const int*)d_in[3];
    const int*   colseg = (const int*)d_in[4];
    float* out = (float*)d_out;

    int n_atoms   = in_sizes[0] / D_FEAT;
    int n_support = in_sizes[1] / D_FEAT;
    int n_struct  = out_size;

    cudaFuncSetAttribute(k_quad_mma, cudaFuncAttributeMaxDynamicSharedMemorySize,
                         SM2_TOTAL);

    k_zero<<<(D_FEAT * D_FEAT + 255) / 256, 256>>>(out, n_struct);

    dim3 gM(16, NSPLIT);
    k_build_M<<<gM, 256>>>(S, W, colseg, n_support);

    k_convM<<<(D_FEAT * D_FEAT) / 256, 256>>>();

    int gQ = (n_atoms + QM - 1) / QM;
    k_quad_mma<<<gQ, 512, SM2_TOTAL>>>(X, rowseg, out, n_atoms);
}

// round 4
// speedup vs baseline: 2.0355x; 1.3867x over previous
#include <cuda_runtime.h>
#include <cuda_bf16.h>
#include <cstdint>

// ============================================================================
// FullGap: out[s] = sum_{i in s} (p_i^T M p_i)/(p_i.p_i),
//          M = sum_j w[colseg[j]] s_j s_j^T  (256x256 symmetric)
// Exact algebra: x^T M x = 2 x^T U x, U = strict-upper(M) + diag(M)/2.
// Pipeline: prep(wvec) -> convX(X->bf16 hi/lo + rnorm) -> build_M (fp32,
// upper tiles only, split-K partials) -> convM (reduce+triangular+bf16 split)
// -> quad (HMMA 3-split, cp.async double-buffered, triangular block skip).
// ============================================================================

#define D_FEAT 256
#define KC 16
#define NSPLIT 32
#define QM 128

__device__ float g_part[NSPLIT][D_FEAT * D_FEAT];              // 8 MB scratch
__device__ __align__(16) __nv_bfloat16 g_Uhi[D_FEAT * D_FEAT]; // [n][a] layout
__device__ __align__(16) __nv_bfloat16 g_Ulo[D_FEAT * D_FEAT];
__device__ __align__(16) __nv_bfloat16 g_Xhi[32768 * D_FEAT];
__device__ __align__(16) __nv_bfloat16 g_Xlo[32768 * D_FEAT];
__device__ float g_rnorm[32768];
__device__ float g_wvec[8192];

// ---------------- helpers ---------------------------------------------------
__device__ __forceinline__ uint32_t smem_u32(const void* p) {
    uint32_t a;
    asm("{ .reg .u64 t; cvta.to.shared.u64 t, %1; cvt.u32.u64 %0, t; }"
        : "=r"(a) : "l"(p));
    return a;
}
__device__ __forceinline__ uint32_t sw_off(uint32_t off) {
    return off ^ ((off >> 3) & 0x70);
}
__device__ __forceinline__ void cpa16(uint32_t dst, const void* src) {
    asm volatile("cp.async.cg.shared.global [%0], [%1], 16;"
                 :: "r"(dst), "l"(__cvta_generic_to_global(src)) : "memory");
}
#define CP_COMMIT() asm volatile("cp.async.commit_group;" ::: "memory")
#define CP_WAIT0()  asm volatile("cp.async.wait_group 0;" ::: "memory")

__device__ __forceinline__ unsigned long long pk2(float lo, float hi) {
    unsigned long long r;
    asm("mov.b64 %0, {%1,%2};" : "=l"(r) : "f"(lo), "f"(hi));
    return r;
}
__device__ __forceinline__ float2 up2(unsigned long long v) {
    float2 f;
    asm("mov.b64 {%0,%1}, %2;" : "=f"(f.x), "=f"(f.y) : "l"(v));
    return f;
}
__device__ __forceinline__ void ffma2(unsigned long long& d,
                                      unsigned long long a,
                                      unsigned long long b) {
    asm("fma.rn.f32x2 %0, %1, %2, %3;" : "=l"(d) : "l"(a), "l"(b), "l"(d));
}
__device__ __forceinline__ void ldsmA(uint32_t base, int rb, int kk, int lane,
                                      uint32_t* a) {
    int g = lane >> 3, r = lane & 7;
    int row = rb + r + (g & 1) * 8;
    int col = kk + (g >> 1) * 8;
    uint32_t addr = base + sw_off((uint32_t)(row * 128 + col * 2));
    asm volatile("ldmatrix.sync.aligned.m8n8.x4.shared.b16 {%0,%1,%2,%3}, [%4];"
                 : "=r"(a[0]), "=r"(a[1]), "=r"(a[2]), "=r"(a[3]) : "r"(addr));
}
__device__ __forceinline__ void ldsmB(uint32_t base, int nb, int kk, int lane,
                                      uint32_t* b) {
    int g = lane >> 3, r = lane & 7;
    int row = nb + r + (g >> 1) * 8;
    int col = kk + (g & 1) * 8;
    uint32_t addr = base + sw_off((uint32_t)(row * 128 + col * 2));
    asm volatile("ldmatrix.sync.aligned.m8n8.x4.shared.b16 {%0,%1,%2,%3}, [%4];"
                 : "=r"(b[0]), "=r"(b[1]), "=r"(b[2]), "=r"(b[3]) : "r"(addr));
}
__device__ __forceinline__ void mma16816(float* c, const uint32_t* a,
                                         const uint32_t* b) {
    asm volatile(
        "mma.sync.aligned.m16n8k16.row.col.f32.bf16.bf16.f32 "
        "{%0,%1,%2,%3}, {%4,%5,%6,%7}, {%8,%9}, {%0,%1,%2,%3};"
        : "+f"(c[0]), "+f"(c[1]), "+f"(c[2]), "+f"(c[3])
        : "r"(a[0]), "r"(a[1]), "r"(a[2]), "r"(a[3]), "r"(b[0]), "r"(b[1]));
}
__device__ __forceinline__ void bsplit(float x, float y, uint32_t& hi, uint32_t& lo) {
    float hx = __bfloat162float(__float2bfloat16(x));
    float hy = __bfloat162float(__float2bfloat16(y));
    __nv_bfloat162 h = __floats2bfloat162_rn(hx, hy);
    __nv_bfloat162 l = __floats2bfloat162_rn(x - hx, y - hy);
    hi = *(uint32_t*)&h;
    lo = *(uint32_t*)&l;
}

// ---- kernel: wvec[j] = W[colseg[j]] ----------------------------------------
__global__ void k_prep(const float* __restrict__ W,
                       const int* __restrict__ colseg, int n_support) {
    int j = blockIdx.x * blockDim.x + threadIdx.x;
    if (j < n_support) g_wvec[j] = W[colseg[j]];
}

// ---- kernel: X -> bf16 hi/lo + rnorm ----------------------------------------
__global__ void __launch_bounds__(256)
k_convX(const float* __restrict__ X, int n_atoms) {
    int warp = (blockIdx.x * blockDim.x + threadIdx.x) >> 5;
    int lane = threadIdx.x & 31;
    if (warp >= n_atoms) return;
    const float4* xp = (const float4*)&X[(size_t)warp * D_FEAT + lane * 8];
    float4 v0 = xp[0];
    float4 v1 = xp[1];
    uint4 h, l;
    bsplit(v0.x, v0.y, h.x, l.x);
    bsplit(v0.z, v0.w, h.y, l.y);
    bsplit(v1.x, v1.y, h.z, l.z);
    bsplit(v1.z, v1.w, h.w, l.w);
    *(uint4*)&g_Xhi[(size_t)warp * D_FEAT + lane * 8] = h;
    *(uint4*)&g_Xlo[(size_t)warp * D_FEAT + lane * 8] = l;
    float nn = v0.x * v0.x + v0.y * v0.y + v0.z * v0.z + v0.w * v0.w +
               v1.x * v1.x + v1.y * v1.y + v1.z * v1.z + v1.w * v1.w;
#pragma unroll
    for (int off = 16; off > 0; off >>= 1)
        nn += __shfl_xor_sync(0xFFFFFFFFu, nn, off);
    if (lane == 0) g_rnorm[warp] = 1.0f / nn;
}

// ---- kernel: M partials (upper-triangular tiles only) ------------------------
__global__ void __launch_bounds__(256)
k_build_M(const float* __restrict__ S, int n_support) {
    __shared__ __align__(16) float sa[KC][64];
    __shared__ __align__(16) float sb[KC][64];

    const int ta_lut[10] = {0, 0, 0, 0, 1, 1, 1, 2, 2, 3};
    const int tb_lut[10] = {0, 1, 2, 3, 1, 2, 3, 2, 3, 3};
    const int a0 = ta_lut[blockIdx.x] * 64;
    const int b0 = tb_lut[blockIdx.x] * 64;
    const int split = blockIdx.y;
    const int span   = (n_support + NSPLIT - 1) / NSPLIT;
    const int jstart = split * span;
    const int jend   = min(jstart + span, n_support);

    const int t  = threadIdx.x;
    const int tx = t & 15;
    const int ty = t >> 4;

    unsigned long long acc[4][2];
#pragma unroll
    for (int r = 0; r < 4; r++) { acc[r][0] = pk2(0.f, 0.f); acc[r][1] = pk2(0.f, 0.f); }

    for (int j0 = jstart; j0 < jend; j0 += KC) {
#pragma unroll
        for (int e = 0; e < 4; e++) {
            int kk  = (t >> 6) + 4 * e;
            int col = t & 63;
            int j = j0 + kk;
            float va = 0.f, vb = 0.f;
            if (j < jend) {
                va = S[(size_t)j * D_FEAT + a0 + col];
                vb = S[(size_t)j * D_FEAT + b0 + col] * g_wvec[j];
            }
            sa[kk][col] = va;
            sb[kk][col] = vb;
        }
        __syncthreads();
#pragma unroll
        for (int kk = 0; kk < KC; kk++) {
            float4 av = *(const float4*)&sa[kk][ty * 4];
            float4 bv = *(const float4*)&sb[kk][tx * 4];
            unsigned long long b01 = pk2(bv.x, bv.y);
            unsigned long long b23 = pk2(bv.z, bv.w);
            float ar[4] = {av.x, av.y, av.z, av.w};
#pragma unroll
            for (int r = 0; r < 4; r++) {
                unsigned long long a2 = pk2(ar[r], ar[r]);
                ffma2(acc[r][0], a2, b01);
                ffma2(acc[r][1], a2, b23);
            }
        }
        __syncthreads();
    }

#pragma unroll
    for (int r = 0; r < 4; r++) {
        float2 c01 = up2(acc[r][0]);
        float2 c23 = up2(acc[r][1]);
        int row = a0 + ty * 4 + r;
        *(float4*)&g_part[split][(size_t)row * D_FEAT + b0 + tx * 4] =
            make_float4(c01.x, c01.y, c23.x, c23.y);
    }
}

// ---- kernel: reduce partials, triangular scale, bf16 split -------------------
// Stores U in B layout: g_U[n*256 + a] = (a<n ? M[a,n] : a==n ? M/2 : 0)
__global__ void k_convM(float* __restrict__ out, int n_struct) {
    int i = blockIdx.x * blockDim.x + threadIdx.x;   // 65536
    if (i < n_struct) out[i] = 0.f;
    int a = i & 255, n = i >> 8;
    float v = 0.f;
    if (a <= n) {
#pragma unroll
        for (int s = 0; s < NSPLIT; s++) v += g_part[s][a * D_FEAT + n];
        if (a == n) v *= 0.5f;
    }
    __nv_bfloat16 h = __float2bfloat16(v);
    g_Uhi[i] = h;
    g_Ulo[i] = __float2bfloat16(v - __bfloat162float(h));
}

// ---- quad kernel: HMMA, cp.async double buffer, triangular skip -------------
#define STG    98304
#define QA_HI  0
#define QA_LO  16384
#define QB_HI  32768
#define QB_LO  65536
#define QROW_OFF 196608
#define SMQ_TOTAL 197120

__device__ __forceinline__ void issue_chunk(char* smem, uint32_t sbase,
                                            int stage, int c, int row0,
                                            int n_atoms, int t) {
    const int k0 = c * 64;
    uint32_t abase = sbase + stage * STG;
    char* pbase = smem + stage * STG;
    // A: 1024 granules per split, 2 per thread
#pragma unroll
    for (int p = 0; p < 2; p++) {
        int g = t + p * 512;
        int row = g >> 3, kq = g & 7;
        uint32_t so = sw_off((uint32_t)(row * 128 + kq * 16));
        if (row0 + row < n_atoms) {
            size_t src = (size_t)(row0 + row) * D_FEAT + k0 + kq * 8;
            cpa16(abase + QA_HI + so, &g_Xhi[src]);
            cpa16(abase + QA_LO + so, &g_Xlo[src]);
        } else {
            uint4 z = make_uint4(0, 0, 0, 0);
            *(uint4*)(pbase + QA_HI + so) = z;
            *(uint4*)(pbase + QA_LO + so) = z;
        }
    }
    // B: 2048 granules per split, 4 per thread; rows < c*64 are zero -> skip
#pragma unroll
    for (int p = 0; p < 4; p++) {
        int g = t + p * 512;
        int row = g >> 3, kq = g & 7;
        if (row >= c * 64) {
            uint32_t so = sw_off((uint32_t)(row * 128 + kq * 16));
            size_t src = (size_t)row * D_FEAT + k0 + kq * 8;
            cpa16(abase + QB_HI + so, &g_Uhi[src]);
            cpa16(abase + QB_LO + so, &g_Ulo[src]);
        }
    }
}

__global__ void __launch_bounds__(512, 1)
k_quad_mma(const float* __restrict__ X, const int* __restrict__ rowseg,
           float* __restrict__ out, int n_atoms) {
    extern __shared__ char smem[];
    float* qrow = (float*)(smem + QROW_OFF);
    const uint32_t sbase = smem_u32(smem);
    const int t    = threadIdx.x;
    const int lane = t & 31;
    const int w    = t >> 5;
    const int wr   = w & 3;       // SMSP id -> balanced wc mix per SMSP
    const int wc   = w >> 2;
    const int row0 = blockIdx.x * QM;

    if (t < QM) qrow[t] = 0.f;

    float acc[2][8][4];
#pragma unroll
    for (int mt = 0; mt < 2; mt++)
#pragma unroll
        for (int nt = 0; nt < 8; nt++)
#pragma unroll
            for (int e = 0; e < 4; e++) acc[mt][nt][e] = 0.f;

    issue_chunk(smem, sbase, 0, 0, row0, n_atoms, t);
    CP_COMMIT();

#pragma unroll
    for (int c = 0; c < 4; c++) {
        CP_WAIT0();
        __syncthreads();
        if (c < 3) {
            issue_chunk(smem, sbase, (c + 1) & 1, c + 1, row0, n_atoms, t);
            CP_COMMIT();
        }
        if (wc >= c) {
            uint32_t ab = sbase + (c & 1) * STG;
#pragma unroll
            for (int ks = 0; ks < 4; ks++) {
                const int kk = ks * 16;
                uint32_t Ah[2][4], Al[2][4];
                ldsmA(ab + QA_HI, wr * 32 + 0,  kk, lane, Ah[0]);
                ldsmA(ab + QA_HI, wr * 32 + 16, kk, lane, Ah[1]);
                ldsmA(ab + QA_LO, wr * 32 + 0,  kk, lane, Al[0]);
                ldsmA(ab + QA_LO, wr * 32 + 16, kk, lane, Al[1]);
#pragma unroll
                for (int np = 0; np < 4; np++) {
                    uint32_t Bh[4], Bl[4];
                    ldsmB(ab + QB_HI, wc * 64 + np * 16, kk, lane, Bh);
                    ldsmB(ab + QB_LO, wc * 64 + np * 16, kk, lane, Bl);
#pragma unroll
                    for (int mt = 0; mt < 2; mt++) {
#pragma unroll
                        for (int n2 = 0; n2 < 2; n2++) {
                            float* C = acc[mt][np * 2 + n2];
                            mma16816(C, Ah[mt], Bh + n2 * 2);
                            mma16816(C, Ah[mt], Bl + n2 * 2);
                            mma16816(C, Al[mt], Bh + n2 * 2);
                        }
                    }
                }
            }
        }
    }

    // ---- epilogue: q' = x . Y'  (Y' = X U, per-warp cols) ----
#pragma unroll
    for (int mt = 0; mt < 2; mt++) {
#pragma unroll
        for (int half = 0; half < 2; half++) {
            int rloc = wr * 32 + mt * 16 + (lane >> 2) + half * 8;
            int rg   = row0 + rloc;
            float qp = 0.f;
            if (rg < n_atoms) {
#pragma unroll
                for (int nt = 0; nt < 8; nt++) {
                    int col = wc * 64 + nt * 8 + (lane & 3) * 2;
                    float2 xv = *(const float2*)&X[(size_t)rg * D_FEAT + col];
                    qp = fmaf(xv.x, acc[mt][nt][half * 2 + 0], qp);
                    qp = fmaf(xv.y, acc[mt][nt][half * 2 + 1], qp);
                }
            }
            qp += __shfl_xor_sync(0xFFFFFFFFu, qp, 1);
            qp += __shfl_xor_sync(0xFFFFFFFFu, qp, 2);
            if ((lane & 3) == 0) atomicAdd(&qrow[rloc], qp);
        }
    }
    __syncthreads();

    if (t < QM) {
        int rg = row0 + t;
        if (rg < n_atoms)
            atomicAdd(&out[rowseg[rg]], 2.0f * qrow[t] * g_rnorm[rg]);
    }
}

// ---- launch ------------------------------------------------------------------
extern "C" void kernel_launch(void* const* d_in, const int* in_sizes, int n_in,
                              void* d_out, int out_size) {
    const float* X      = (const float*)d_in[0];
    const float* S      = (const float*)d_in[1];
    const float* W      = (const float*)d_in[2];
    const int*   rowseg = (const int*)d_in[3];
    const int*   colseg = (const int*)d_in[4];
    float* out = (float*)d_out;

    int n_atoms   = in_sizes[0] / D_FEAT;
    int n_support = in_sizes[1] / D_FEAT;
    int n_struct  = out_size;

    cudaFuncSetAttribute(k_quad_mma, cudaFuncAttributeMaxDynamicSharedMemorySize,
                         SMQ_TOTAL);

    k_prep<<<(n_support + 255) / 256, 256>>>(W, colseg, n_support);
    k_convX<<<(n_atoms + 7) / 8, 256>>>(X, n_atoms);
    dim3 gM(10, NSPLIT);
    k_build_M<<<gM, 256>>>(S, n_support);
    k_convM<<<D_FEAT * D_FEAT / 256, 256>>>(out, n_struct);
    int gQ = (n_atoms + QM - 1) / QM;
    k_quad_mma<<<gQ, 512, SMQ_TOTAL>>>(X, rowseg, out, n_atoms);
}

// round 5
// speedup vs baseline: 2.2154x; 1.0884x over previous
#include <cuda_runtime.h>
#include <cuda_bf16.h>
#include <cstdint>

// ============================================================================
// FullGap: out[s] = sum_{i in s} (p_i^T M p_i)/(p_i.p_i),
//          M = sum_j w[colseg[j]] s_j s_j^T  (256x256 symmetric)
// x^T M x = 2 x^T U x,  U = strict-upper(M) + diag(M)/2.
// Pipeline: prep(zero+wvec) -> convX -> convS -> build_mma (HMMA 3-split,
// ldmatrix.trans, atomic fp32 into M^T) -> convM (coalesced, bf16 split)
// -> quad (HMMA 3-split, cp.async double-buffered, triangular block skip).
// ============================================================================

#define D_FEAT 256
#define QM 128

__device__ float g_MT[D_FEAT * D_FEAT];                         // [b][a] layout
__device__ __align__(16) __nv_bfloat16 g_Uhi[D_FEAT * D_FEAT];  // [n][a]
__device__ __align__(16) __nv_bfloat16 g_Ulo[D_FEAT * D_FEAT];
__device__ __align__(16) __nv_bfloat16 g_Xhi[32768 * D_FEAT];
__device__ __align__(16) __nv_bfloat16 g_Xlo[32768 * D_FEAT];
__device__ __align__(16) __nv_bfloat16 g_Shi[8192 * D_FEAT];
__device__ __align__(16) __nv_bfloat16 g_Slo[8192 * D_FEAT];
__device__ __align__(16) __nv_bfloat16 g_SWhi[8192 * D_FEAT];
__device__ __align__(16) __nv_bfloat16 g_SWlo[8192 * D_FEAT];
__device__ float g_rnorm[32768];
__device__ float g_wvec[8192];

// ---------------- helpers ----------------------------------------------------
__device__ __forceinline__ uint32_t smem_u32(const void* p) {
    uint32_t a;
    asm("{ .reg .u64 t; cvta.to.shared.u64 t, %1; cvt.u32.u64 %0, t; }"
        : "=r"(a) : "l"(p));
    return a;
}
__device__ __forceinline__ uint32_t sw_off(uint32_t off) {
    return off ^ ((off >> 3) & 0x70);
}
__device__ __forceinline__ void cpa16(uint32_t dst, const void* src) {
    asm volatile("cp.async.cg.shared.global [%0], [%1], 16;"
                 :: "r"(dst), "l"(__cvta_generic_to_global(src)) : "memory");
}
#define CP_COMMIT() asm volatile("cp.async.commit_group;" ::: "memory")
#define CP_WAIT0()  asm volatile("cp.async.wait_group 0;" ::: "memory")

// non-trans A: smem[m][k]
__device__ __forceinline__ void ldsmA(uint32_t base, int rb, int kk, int lane,
                                      uint32_t* a) {
    int g = lane >> 3, r = lane & 7;
    int row = rb + r + (g & 1) * 8;
    int col = kk + (g >> 1) * 8;
    uint32_t addr = base + sw_off((uint32_t)(row * 128 + col * 2));
    asm volatile("ldmatrix.sync.aligned.m8n8.x4.shared.b16 {%0,%1,%2,%3}, [%4];"
                 : "=r"(a[0]), "=r"(a[1]), "=r"(a[2]), "=r"(a[3]) : "r"(addr));
}
// non-trans B: smem[n][k]
__device__ __forceinline__ void ldsmB(uint32_t base, int nb, int kk, int lane,
                                      uint32_t* b) {
    int g = lane >> 3, r = lane & 7;
    int row = nb + r + (g >> 1) * 8;
    int col = kk + (g & 1) * 8;
    uint32_t addr = base + sw_off((uint32_t)(row * 128 + col * 2));
    asm volatile("ldmatrix.sync.aligned.m8n8.x4.shared.b16 {%0,%1,%2,%3}, [%4];"
                 : "=r"(b[0]), "=r"(b[1]), "=r"(b[2]), "=r"(b[3]) : "r"(addr));
}
// trans A: smem[k][m], panelized 2x(64 cols * 128B rows)
__device__ __forceinline__ void ldsmA_t(uint32_t base, int ab, int kk, int lane,
                                        uint32_t* a) {
    int g = lane >> 3, r = lane & 7;
    int row = kk + r + (g >> 1) * 8;
    int col = ab + (g & 1) * 8;
    uint32_t addr = base + (uint32_t)(col >> 6) * 8192 +
                    sw_off((uint32_t)(row * 128 + (col & 63) * 2));
    asm volatile("ldmatrix.sync.aligned.m8n8.x4.trans.shared.b16 {%0,%1,%2,%3}, [%4];"
                 : "=r"(a[0]), "=r"(a[1]), "=r"(a[2]), "=r"(a[3]) : "r"(addr));
}
// trans B: smem[k][n], panelized
__device__ __forceinline__ void ldsmB_t(uint32_t base, int nb, int kk, int lane,
                                        uint32_t* b) {
    int g = lane >> 3, r = lane & 7;
    int row = kk + r + (g & 1) * 8;
    int col = nb + (g >> 1) * 8;
    uint32_t addr = base + (uint32_t)(col >> 6) * 8192 +
                    sw_off((uint32_t)(row * 128 + (col & 63) * 2));
    asm volatile("ldmatrix.sync.aligned.m8n8.x4.trans.shared.b16 {%0,%1,%2,%3}, [%4];"
                 : "=r"(b[0]), "=r"(b[1]), "=r"(b[2]), "=r"(b[3]) : "r"(addr));
}
__device__ __forceinline__ void mma16816(float* c, const uint32_t* a,
                                         const uint32_t* b) {
    asm volatile(
        "mma.sync.aligned.m16n8k16.row.col.f32.bf16.bf16.f32 "
        "{%0,%1,%2,%3}, {%4,%5,%6,%7}, {%8,%9}, {%0,%1,%2,%3};"
        : "+f"(c[0]), "+f"(c[1]), "+f"(c[2]), "+f"(c[3])
        : "r"(a[0]), "r"(a[1]), "r"(a[2]), "r"(a[3]), "r"(b[0]), "r"(b[1]));
}
__device__ __forceinline__ void bsplit(float x, float y, uint32_t& hi, uint32_t& lo) {
    float hx = __bfloat162float(__float2bfloat16(x));
    float hy = __bfloat162float(__float2bfloat16(y));
    __nv_bfloat162 h = __floats2bfloat162_rn(hx, hy);
    __nv_bfloat162 l = __floats2bfloat162_rn(x - hx, y - hy);
    hi = *(uint32_t*)&h;
    lo = *(uint32_t*)&l;
}

// ---- prep: zero M^T + out, wvec ----------------------------------------------
__global__ void k_prep(const float* __restrict__ W,
                       const int* __restrict__ colseg, int n_support,
                       float* __restrict__ out, int n_struct) {
    int i = blockIdx.x * blockDim.x + threadIdx.x;   // 65536
    g_MT[i] = 0.f;
    if (i < n_struct) out[i] = 0.f;
    if (i < n_support) g_wvec[i] = W[colseg[i]];
}

// ---- convX: X -> bf16 hi/lo + rnorm -------------------------------------------
__global__ void __launch_bounds__(256)
k_convX(const float* __restrict__ X, int n_atoms) {
    int warp = (blockIdx.x * blockDim.x + threadIdx.x) >> 5;
    int lane = threadIdx.x & 31;
    if (warp >= n_atoms) return;
    const float4* xp = (const float4*)&X[(size_t)warp * D_FEAT + lane * 8];
    float4 v0 = xp[0];
    float4 v1 = xp[1];
    uint4 h, l;
    bsplit(v0.x, v0.y, h.x, l.x);
    bsplit(v0.z, v0.w, h.y, l.y);
    bsplit(v1.x, v1.y, h.z, l.z);
    bsplit(v1.z, v1.w, h.w, l.w);
    *(uint4*)&g_Xhi[(size_t)warp * D_FEAT + lane * 8] = h;
    *(uint4*)&g_Xlo[(size_t)warp * D_FEAT + lane * 8] = l;
    float nn = v0.x * v0.x + v0.y * v0.y + v0.z * v0.z + v0.w * v0.w +
               v1.x * v1.x + v1.y * v1.y + v1.z * v1.z + v1.w * v1.w;
#pragma unroll
    for (int off = 16; off > 0; off >>= 1)
        nn += __shfl_xor_sync(0xFFFFFFFFu, nn, off);
    if (lane == 0) g_rnorm[warp] = 1.0f / nn;
}

// ---- convS: S -> bf16 hi/lo and (w*S) -> bf16 hi/lo ---------------------------
__global__ void __launch_bounds__(256)
k_convS(const float* __restrict__ S, int n_support) {
    int warp = (blockIdx.x * blockDim.x + threadIdx.x) >> 5;
    int lane = threadIdx.x & 31;
    if (warp >= n_support) return;
    float w = g_wvec[warp];
    const float4* sp = (const float4*)&S[(size_t)warp * D_FEAT + lane * 8];
    float4 v0 = sp[0];
    float4 v1 = sp[1];
    uint4 h, l;
    bsplit(v0.x, v0.y, h.x, l.x);
    bsplit(v0.z, v0.w, h.y, l.y);
    bsplit(v1.x, v1.y, h.z, l.z);
    bsplit(v1.z, v1.w, h.w, l.w);
    *(uint4*)&g_Shi[(size_t)warp * D_FEAT + lane * 8] = h;
    *(uint4*)&g_Slo[(size_t)warp * D_FEAT + lane * 8] = l;
    bsplit(w * v0.x, w * v0.y, h.x, l.x);
    bsplit(w * v0.z, w * v0.w, h.y, l.y);
    bsplit(w * v1.x, w * v1.y, h.z, l.z);
    bsplit(w * v1.z, w * v1.w, h.w, l.w);
    *(uint4*)&g_SWhi[(size_t)warp * D_FEAT + lane * 8] = h;
    *(uint4*)&g_SWlo[(size_t)warp * D_FEAT + lane * 8] = l;
}

// ---- build: M[a,b] = sum_j S[j][a] * wS[j][b], HMMA 3-split -------------------
// Grid: 3 upper 128x128 tiles x 16 splitK. 512 thr. K = 512 j per CTA, chunks 64.
// SMEM stage: SA_hi 16K | SA_lo 16K | SB_hi 16K | SB_lo 16K ; x2 stages = 128K.
#define BSTG 65536
#define BA_HI 0
#define BA_LO 16384
#define BB_HI 32768
#define BB_LO 49152
#define SMB_TOTAL 131072

__device__ __forceinline__ void b_issue(uint32_t sbase, int stage, int jb,
                                        int a0, int b0, int n_support, int t,
                                        char* smem) {
    const __nv_bfloat16* srcs[4] = {g_Shi, g_Slo, g_SWhi, g_SWlo};
    uint32_t ab = sbase + stage * BSTG;
#pragma unroll
    for (int p = 0; p < 8; p++) {
        int g = t + p * 512;          // 4096 granules
        int arr  = g >> 10;
        int rem  = g & 1023;
        int row  = rem >> 4;          // j local 0..63
        int gran = rem & 15;          // 16B granule in 256B row
        int cbase = (arr < 2) ? a0 : b0;
        uint32_t dst = ab + arr * 16384 + (uint32_t)(gran >> 3) * 8192 +
                       sw_off((uint32_t)(row * 128 + (gran & 7) * 16));
        int j = jb + row;
        if (j < n_support) {
            cpa16(dst, &srcs[arr][(size_t)j * D_FEAT + cbase + gran * 8]);
        } else {
            *(uint4*)(smem + (dst - sbase)) = make_uint4(0, 0, 0, 0);
        }
    }
}

__global__ void __launch_bounds__(512, 1)
k_build_mma(int n_support) {
    extern __shared__ char smem[];
    const uint32_t sbase = smem_u32(smem);
    const int t    = threadIdx.x;
    const int lane = t & 31;
    const int w    = t >> 5;
    const int wr   = w & 3;
    const int wc   = w >> 2;

    const int ta_lut[3] = {0, 0, 1};
    const int tb_lut[3] = {0, 1, 1};
    const int tile  = blockIdx.x % 3;
    const int split = blockIdx.x / 3;
    const int a0 = ta_lut[tile] * 128;
    const int b0 = tb_lut[tile] * 128;
    const int jbase = split * 512;

    float acc[2][4][4];
#pragma unroll
    for (int mt = 0; mt < 2; mt++)
#pragma unroll
        for (int nt = 0; nt < 4; nt++)
#pragma unroll
            for (int e = 0; e < 4; e++) acc[mt][nt][e] = 0.f;

    b_issue(sbase, 0, jbase, a0, b0, n_support, t, smem);
    CP_COMMIT();

#pragma unroll 1
    for (int c = 0; c < 8; c++) {
        CP_WAIT0();
        __syncthreads();
        if (c < 7) {
            b_issue(sbase, (c + 1) & 1, jbase + (c + 1) * 64, a0, b0,
                    n_support, t, smem);
            CP_COMMIT();
        }
        uint32_t ab = sbase + (c & 1) * BSTG;
#pragma unroll
        for (int ks = 0; ks < 4; ks++) {
            const int kk = ks * 16;
            uint32_t Ah[2][4], Al[2][4];
            ldsmA_t(ab + BA_HI, wr * 32 + 0,  kk, lane, Ah[0]);
            ldsmA_t(ab + BA_HI, wr * 32 + 16, kk, lane, Ah[1]);
            ldsmA_t(ab + BA_LO, wr * 32 + 0,  kk, lane, Al[0]);
            ldsmA_t(ab + BA_LO, wr * 32 + 16, kk, lane, Al[1]);
#pragma unroll
            for (int np = 0; np < 2; np++) {
                uint32_t Bh[4], Bl[4];
                ldsmB_t(ab + BB_HI, wc * 32 + np * 16, kk, lane, Bh);
                ldsmB_t(ab + BB_LO, wc * 32 + np * 16, kk, lane, Bl);
#pragma unroll
                for (int mt = 0; mt < 2; mt++) {
#pragma unroll
                    for (int n2 = 0; n2 < 2; n2++) {
                        float* C = acc[mt][np * 2 + n2];
                        mma16816(C, Ah[mt], Bh + n2 * 2);
                        mma16816(C, Ah[mt], Bl + n2 * 2);
                        mma16816(C, Al[mt], Bh + n2 * 2);
                    }
                }
            }
        }
        __syncthreads();
    }

    // epilogue: atomic fp32 into M^T ([b][a] layout)
#pragma unroll
    for (int mt = 0; mt < 2; mt++) {
#pragma unroll
        for (int nt = 0; nt < 4; nt++) {
#pragma unroll
            for (int e = 0; e < 4; e++) {
                int a = a0 + wr * 32 + mt * 16 + (lane >> 2) + (e >> 1) * 8;
                int b = b0 + wc * 32 + nt * 8 + (lane & 3) * 2 + (e & 1);
                atomicAdd(&g_MT[b * D_FEAT + a], acc[mt][nt][e]);
            }
        }
    }
}

// ---- convM: M^T -> U bf16 hi/lo (fully coalesced) -----------------------------
__global__ void k_convM() {
    int i = blockIdx.x * blockDim.x + threadIdx.x;   // 65536, i = n*256+a
    int a = i & 255, n = i >> 8;
    float v = g_MT[i];
    v = (a < n) ? v : (a == n ? 0.5f * v : 0.f);
    __nv_bfloat16 h = __float2bfloat16(v);
    g_Uhi[i] = h;
    g_Ulo[i] = __float2bfloat16(v - __bfloat162float(h));
}

// ---- quad kernel (unchanged from R4) ------------------------------------------
#define STG    98304
#define QA_HI  0
#define QA_LO  16384
#define QB_HI  32768
#define QB_LO  65536
#define QROW_OFF 196608
#define SMQ_TOTAL 197120

__device__ __forceinline__ void issue_chunk(char* smem, uint32_t sbase,
                                            int stage, int c, int row0,
                                            int n_atoms, int t) {
    const int k0 = c * 64;
    uint32_t abase = sbase + stage * STG;
    char* pbase = smem + stage * STG;
#pragma unroll
    for (int p = 0; p < 2; p++) {
        int g = t + p * 512;
        int row = g >> 3, kq = g & 7;
        uint32_t so = sw_off((uint32_t)(row * 128 + kq * 16));
        if (row0 + row < n_atoms) {
            size_t src = (size_t)(row0 + row) * D_FEAT + k0 + kq * 8;
            cpa16(abase + QA_HI + so, &g_Xhi[src]);
            cpa16(abase + QA_LO + so, &g_Xlo[src]);
        } else {
            uint4 z = make_uint4(0, 0, 0, 0);
            *(uint4*)(pbase + QA_HI + so) = z;
            *(uint4*)(pbase + QA_LO + so) = z;
        }
    }
#pragma unroll
    for (int p = 0; p < 4; p++) {
        int g = t + p * 512;
        int row = g >> 3, kq = g & 7;
        if (row >= c * 64) {
            uint32_t so = sw_off((uint32_t)(row * 128 + kq * 16));
            size_t src = (size_t)row * D_FEAT + k0 + kq * 8;
            cpa16(abase + QB_HI + so, &g_Uhi[src]);
            cpa16(abase + QB_LO + so, &g_Ulo[src]);
        }
    }
}

__global__ void __launch_bounds__(512, 1)
k_quad_mma(const float* __restrict__ X, const int* __restrict__ rowseg,
           float* __restrict__ out, int n_atoms) {
    extern __shared__ char smem[];
    float* qrow = (float*)(smem + QROW_OFF);
    const uint32_t sbase = smem_u32(smem);
    const int t    = threadIdx.x;
    const int lane = t & 31;
    const int w    = t >> 5;
    const int wr   = w & 3;
    const int wc   = w >> 2;
    const int row0 = blockIdx.x * QM;

    if (t < QM) qrow[t] = 0.f;

    float acc[2][8][4];
#pragma unroll
    for (int mt = 0; mt < 2; mt++)
#pragma unroll
        for (int nt = 0; nt < 8; nt++)
#pragma unroll
            for (int e = 0; e < 4; e++) acc[mt][nt][e] = 0.f;

    issue_chunk(smem, sbase, 0, 0, row0, n_atoms, t);
    CP_COMMIT();

#pragma unroll
    for (int c = 0; c < 4; c++) {
        CP_WAIT0();
        __syncthreads();
        if (c < 3) {
            issue_chunk(smem, sbase, (c + 1) & 1, c + 1, row0, n_atoms, t);
            CP_COMMIT();
        }
        if (wc >= c) {
            uint32_t ab = sbase + (c & 1) * STG;
#pragma unroll
            for (int ks = 0; ks < 4; ks++) {
                const int kk = ks * 16;
                uint32_t Ah[2][4], Al[2][4];
                ldsmA(ab + QA_HI, wr * 32 + 0,  kk, lane, Ah[0]);
                ldsmA(ab + QA_HI, wr * 32 + 16, kk, lane, Ah[1]);
                ldsmA(ab + QA_LO, wr * 32 + 0,  kk, lane, Al[0]);
                ldsmA(ab + QA_LO, wr * 32 + 16, kk, lane, Al[1]);
#pragma unroll
                for (int np = 0; np < 4; np++) {
                    uint32_t Bh[4], Bl[4];
                    ldsmB(ab + QB_HI, wc * 64 + np * 16, kk, lane, Bh);
                    ldsmB(ab + QB_LO, wc * 64 + np * 16, kk, lane, Bl);
#pragma unroll
                    for (int mt = 0; mt < 2; mt++) {
#pragma unroll
                        for (int n2 = 0; n2 < 2; n2++) {
                            float* C = acc[mt][np * 2 + n2];
                            mma16816(C, Ah[mt], Bh + n2 * 2);
                            mma16816(C, Ah[mt], Bl + n2 * 2);
                            mma16816(C, Al[mt], Bh + n2 * 2);
                        }
                    }
                }
            }
        }
    }

#pragma unroll
    for (int mt = 0; mt < 2; mt++) {
#pragma unroll
        for (int half = 0; half < 2; half++) {
            int rloc = wr * 32 + mt * 16 + (lane >> 2) + half * 8;
            int rg   = row0 + rloc;
            float qp = 0.f;
            if (rg < n_atoms) {
#pragma unroll
                for (int nt = 0; nt < 8; nt++) {
                    int col = wc * 64 + nt * 8 + (lane & 3) * 2;
                    float2 xv = *(const float2*)&X[(size_t)rg * D_FEAT + col];
                    qp = fmaf(xv.x, acc[mt][nt][half * 2 + 0], qp);
                    qp = fmaf(xv.y, acc[mt][nt][half * 2 + 1], qp);
                }
            }
            qp += __shfl_xor_sync(0xFFFFFFFFu, qp, 1);
            qp += __shfl_xor_sync(0xFFFFFFFFu, qp, 2);
            if ((lane & 3) == 0) atomicAdd(&qrow[rloc], qp);
        }
    }
    __syncthreads();

    if (t < QM) {
        int rg = row0 + t;
        if (rg < n_atoms)
            atomicAdd(&out[rowseg[rg]], 2.0f * qrow[t] * g_rnorm[rg]);
    }
}

// ---- launch --------------------------------------------------------------------
extern "C" void kernel_launch(void* const* d_in, const int* in_sizes, int n_in,
                              void* d_out, int out_size) {
    const float* X      = (const float*)d_in[0];
    const float* S      = (const float*)d_in[1];
    const float* W      = (const float*)d_in[2];
    const int*   rowseg = (const int*)d_in[3];
    const int*   colseg = (const int*)d_in[4];
    float* out = (float*)d_out;

    int n_atoms   = in_sizes[0] / D_FEAT;
    int n_support = in_sizes[1] / D_FEAT;
    int n_struct  = out_size;

    cudaFuncSetAttribute(k_quad_mma, cudaFuncAttributeMaxDynamicSharedMemorySize,
                         SMQ_TOTAL);
    cudaFuncSetAttribute(k_build_mma, cudaFuncAttributeMaxDynamicSharedMemorySize,
                         SMB_TOTAL);

    k_prep<<<D_FEAT * D_FEAT / 256, 256>>>(W, colseg, n_support, out, n_struct);
    k_convX<<<(n_atoms + 7) / 8, 256>>>(X, n_atoms);
    k_convS<<<(n_support + 7) / 8, 256>>>(S, n_support);
    k_build_mma<<<48, 512, SMB_TOTAL>>>(n_support);
    k_convM<<<D_FEAT * D_FEAT / 256, 256>>>();
    int gQ = (n_atoms + QM - 1) / QM;
    k_quad_mma<<<gQ, 512, SMQ_TOTAL>>>(X, rowseg, out, n_atoms);
}

// round 6
// speedup vs baseline: 2.5329x; 1.1433x over previous
#include <cuda_runtime.h>
#include <cuda_bf16.h>
#include <cstdint>

// ============================================================================
// FullGap: out[s] = sum_{i in s} (p_i^T M p_i)/(p_i.p_i),
//          M = sum_j w[colseg[j]] s_j s_j^T  (256x256 symmetric)
// x^T M x = 2 x^T U x,  U = strict-upper(M) + diag(M)/2.
// R6 pipeline: convX (X->bf16 hi/lo + rnorm) ->
//   build (HMMA 3-split, inline S conversion, 192 CTAs, coalesced partials) ->
//   convM (reduce partials, triangular, bf16 split, zero out) ->
//   quad (HMMA 3-split, cp.async double-buffered, triangular block skip).
// ============================================================================

#define D_FEAT 256
#define QM 128

__device__ float g_bpart[192][16384];                           // 12 MB partials
__device__ __align__(16) __nv_bfloat16 g_Uhi[D_FEAT * D_FEAT];  // [n][a]
__device__ __align__(16) __nv_bfloat16 g_Ulo[D_FEAT * D_FEAT];
__device__ __align__(16) __nv_bfloat16 g_Xhi[32768 * D_FEAT];
__device__ __align__(16) __nv_bfloat16 g_Xlo[32768 * D_FEAT];
__device__ float g_rnorm[32768];

// ---------------- helpers ----------------------------------------------------
__device__ __forceinline__ uint32_t smem_u32(const void* p) {
    uint32_t a;
    asm("{ .reg .u64 t; cvta.to.shared.u64 t, %1; cvt.u32.u64 %0, t; }"
        : "=r"(a) : "l"(p));
    return a;
}
__device__ __forceinline__ uint32_t sw_off(uint32_t off) {
    return off ^ ((off >> 3) & 0x70);
}
__device__ __forceinline__ void cpa16(uint32_t dst, const void* src) {
    asm volatile("cp.async.cg.shared.global [%0], [%1], 16;"
                 :: "r"(dst), "l"(__cvta_generic_to_global(src)) : "memory");
}
#define CP_COMMIT() asm volatile("cp.async.commit_group;" ::: "memory")
#define CP_WAIT0()  asm volatile("cp.async.wait_group 0;" ::: "memory")

// non-trans A: smem[m][k] (quad kernel)
__device__ __forceinline__ void ldsmA(uint32_t base, int rb, int kk, int lane,
                                      uint32_t* a) {
    int g = lane >> 3, r = lane & 7;
    int row = rb + r + (g & 1) * 8;
    int col = kk + (g >> 1) * 8;
    uint32_t addr = base + sw_off((uint32_t)(row * 128 + col * 2));
    asm volatile("ldmatrix.sync.aligned.m8n8.x4.shared.b16 {%0,%1,%2,%3}, [%4];"
                 : "=r"(a[0]), "=r"(a[1]), "=r"(a[2]), "=r"(a[3]) : "r"(addr));
}
// non-trans B: smem[n][k] (quad kernel)
__device__ __forceinline__ void ldsmB(uint32_t base, int nb, int kk, int lane,
                                      uint32_t* b) {
    int g = lane >> 3, r = lane & 7;
    int row = nb + r + (g >> 1) * 8;
    int col = kk + (g & 1) * 8;
    uint32_t addr = base + sw_off((uint32_t)(row * 128 + col * 2));
    asm volatile("ldmatrix.sync.aligned.m8n8.x4.shared.b16 {%0,%1,%2,%3}, [%4];"
                 : "=r"(b[0]), "=r"(b[1]), "=r"(b[2]), "=r"(b[3]) : "r"(addr));
}
// trans A: smem[k][m], panels of 128 rows x 64 cols (16 KB)
__device__ __forceinline__ void ldsmT_A(uint32_t base, int ab, int kk, int lane,
                                        uint32_t* a) {
    int g = lane >> 3, r = lane & 7;
    int row = kk + r + (g >> 1) * 8;
    int col = ab + (g & 1) * 8;
    uint32_t addr = base + (uint32_t)(col >> 6) * 16384 +
                    sw_off((uint32_t)(row * 128 + (col & 63) * 2));
    asm volatile("ldmatrix.sync.aligned.m8n8.x4.trans.shared.b16 {%0,%1,%2,%3}, [%4];"
                 : "=r"(a[0]), "=r"(a[1]), "=r"(a[2]), "=r"(a[3]) : "r"(addr));
}
// trans B: smem[k][n], panels of 128 rows x 64 cols
__device__ __forceinline__ void ldsmT_B(uint32_t base, int nb, int kk, int lane,
                                        uint32_t* b) {
    int g = lane >> 3, r = lane & 7;
    int row = kk + r + (g & 1) * 8;
    int col = nb + (g >> 1) * 8;
    uint32_t addr = base + (uint32_t)(col >> 6) * 16384 +
                    sw_off((uint32_t)(row * 128 + (col & 63) * 2));
    asm volatile("ldmatrix.sync.aligned.m8n8.x4.trans.shared.b16 {%0,%1,%2,%3}, [%4];"
                 : "=r"(b[0]), "=r"(b[1]), "=r"(b[2]), "=r"(b[3]) : "r"(addr));
}
__device__ __forceinline__ void mma16816(float* c, const uint32_t* a,
                                         const uint32_t* b) {
    asm volatile(
        "mma.sync.aligned.m16n8k16.row.col.f32.bf16.bf16.f32 "
        "{%0,%1,%2,%3}, {%4,%5,%6,%7}, {%8,%9}, {%0,%1,%2,%3};"
        : "+f"(c[0]), "+f"(c[1]), "+f"(c[2]), "+f"(c[3])
        : "r"(a[0]), "r"(a[1]), "r"(a[2]), "r"(a[3]), "r"(b[0]), "r"(b[1]));
}
__device__ __forceinline__ void bsplit(float x, float y, uint32_t& hi, uint32_t& lo) {
    float hx = __bfloat162float(__float2bfloat16(x));
    float hy = __bfloat162float(__float2bfloat16(y));
    __nv_bfloat162 h = __floats2bfloat162_rn(hx, hy);
    __nv_bfloat162 l = __floats2bfloat162_rn(x - hx, y - hy);
    hi = *(uint32_t*)&h;
    lo = *(uint32_t*)&l;
}

// ---- convX: X -> bf16 hi/lo + rnorm -------------------------------------------
__global__ void __launch_bounds__(256)
k_convX(const float* __restrict__ X, int n_atoms) {
    int warp = (blockIdx.x * blockDim.x + threadIdx.x) >> 5;
    int lane = threadIdx.x & 31;
    if (warp >= n_atoms) return;
    const float4* xp = (const float4*)&X[(size_t)warp * D_FEAT + lane * 8];
    float4 v0 = xp[0];
    float4 v1 = xp[1];
    uint4 h, l;
    bsplit(v0.x, v0.y, h.x, l.x);
    bsplit(v0.z, v0.w, h.y, l.y);
    bsplit(v1.x, v1.y, h.z, l.z);
    bsplit(v1.z, v1.w, h.w, l.w);
    *(uint4*)&g_Xhi[(size_t)warp * D_FEAT + lane * 8] = h;
    *(uint4*)&g_Xlo[(size_t)warp * D_FEAT + lane * 8] = l;
    float nn = v0.x * v0.x + v0.y * v0.y + v0.z * v0.z + v0.w * v0.w +
               v1.x * v1.x + v1.y * v1.y + v1.z * v1.z + v1.w * v1.w;
#pragma unroll
    for (int off = 16; off > 0; off >>= 1)
        nn += __shfl_xor_sync(0xFFFFFFFFu, nn, off);
    if (lane == 0) g_rnorm[warp] = 1.0f / nn;
}

// ---- build: M[a,b] = sum_j S[j][a] * w_j S[j][b], inline conversion -----------
// Grid 192 = 3 tiles x 64 splitK. 512 thr. 128 j per split iteration.
// SMEM: Ahi 32K | Alo 32K | Bhi 32K | Blo 32K | w 512B
#define BA_HI 0
#define BA_LO 32768
#define BB_HI 65536
#define BB_LO 98304
#define BW_OFF 131072
#define SMB_TOTAL 131584

__global__ void __launch_bounds__(512, 1)
k_build_mma(const float* __restrict__ S, const float* __restrict__ W,
            const int* __restrict__ colseg, int n_support) {
    extern __shared__ char smem[];
    const uint32_t sbase = smem_u32(smem);
    float* sw = (float*)(smem + BW_OFF);
    const int t    = threadIdx.x;
    const int lane = t & 31;
    const int w    = t >> 5;
    const int wr   = w & 3;
    const int wc   = w >> 2;

    const int tile  = blockIdx.x >> 6;
    const int split = blockIdx.x & 63;
    const int a0 = (tile == 2) ? 128 : 0;
    const int b0 = (tile == 0) ? 0 : 128;

    float acc[2][4][4];
#pragma unroll
    for (int mt = 0; mt < 2; mt++)
#pragma unroll
        for (int nt = 0; nt < 4; nt++)
#pragma unroll
            for (int e = 0; e < 4; e++) acc[mt][nt][e] = 0.f;

#pragma unroll 1
    for (int jb = split * 128; jb < n_support; jb += 64 * 128) {
        __syncthreads();
        if (t < 128) {
            int jg = jb + t;
            sw[t] = (jg < n_support) ? W[colseg[jg]] : 0.f;
        }
        __syncthreads();

        // A side: S[j][a0+cols] -> hi/lo, trans layout smem[j][col]
#pragma unroll
        for (int p = 0; p < 8; p++) {
            int g  = t + p * 512;        // 4096 granules = 128 j x 32 float4
            int jl = g >> 5, cq = g & 31;
            int jg = jb + jl;
            float4 v = make_float4(0.f, 0.f, 0.f, 0.f);
            if (jg < n_support)
                v = *(const float4*)&S[(size_t)jg * D_FEAT + a0 + cq * 4];
            uint32_t h0, l0, h1, l1;
            bsplit(v.x, v.y, h0, l0);
            bsplit(v.z, v.w, h1, l1);
            uint32_t off = (uint32_t)(cq >> 4) * 16384 +
                           sw_off((uint32_t)(jl * 128 + (cq & 15) * 8));
            *(uint2*)(smem + BA_HI + off) = make_uint2(h0, h1);
            *(uint2*)(smem + BA_LO + off) = make_uint2(l0, l1);
        }
        // B side: w_j * S[j][b0+cols] -> hi/lo
#pragma unroll
        for (int p = 0; p < 8; p++) {
            int g  = t + p * 512;
            int jl = g >> 5, cq = g & 31;
            int jg = jb + jl;
            float4 v = make_float4(0.f, 0.f, 0.f, 0.f);
            if (jg < n_support)
                v = *(const float4*)&S[(size_t)jg * D_FEAT + b0 + cq * 4];
            float wj = sw[jl];
            uint32_t h0, l0, h1, l1;
            bsplit(wj * v.x, wj * v.y, h0, l0);
            bsplit(wj * v.z, wj * v.w, h1, l1);
            uint32_t off = (uint32_t)(cq >> 4) * 16384 +
                           sw_off((uint32_t)(jl * 128 + (cq & 15) * 8));
            *(uint2*)(smem + BB_HI + off) = make_uint2(h0, h1);
            *(uint2*)(smem + BB_LO + off) = make_uint2(l0, l1);
        }
        __syncthreads();

#pragma unroll
        for (int ks = 0; ks < 8; ks++) {
            const int kk = ks * 16;
            uint32_t Ah[2][4], Al[2][4];
            ldsmT_A(sbase + BA_HI, wr * 32 + 0,  kk, lane, Ah[0]);
            ldsmT_A(sbase + BA_HI, wr * 32 + 16, kk, lane, Ah[1]);
            ldsmT_A(sbase + BA_LO, wr * 32 + 0,  kk, lane, Al[0]);
            ldsmT_A(sbase + BA_LO, wr * 32 + 16, kk, lane, Al[1]);
#pragma unroll
            for (int np = 0; np < 2; np++) {
                uint32_t Bh[4], Bl[4];
                ldsmT_B(sbase + BB_HI, wc * 32 + np * 16, kk, lane, Bh);
                ldsmT_B(sbase + BB_LO, wc * 32 + np * 16, kk, lane, Bl);
#pragma unroll
                for (int mt = 0; mt < 2; mt++) {
#pragma unroll
                    for (int n2 = 0; n2 < 2; n2++) {
                        float* C = acc[mt][np * 2 + n2];
                        mma16816(C, Ah[mt], Bh + n2 * 2);
                        mma16816(C, Ah[mt], Bl + n2 * 2);
                        mma16816(C, Al[mt], Bh + n2 * 2);
                    }
                }
            }
        }
    }

    // epilogue: stage acc -> smem [b][a], then coalesced partial store
    __syncthreads();
    float* st = (float*)smem;
#pragma unroll
    for (int mt = 0; mt < 2; mt++)
#pragma unroll
        for (int nt = 0; nt < 4; nt++)
#pragma unroll
            for (int e = 0; e < 4; e++) {
                int a = wr * 32 + mt * 16 + (lane >> 2) + (e >> 1) * 8;
                int b = wc * 32 + nt * 8 + (lane & 3) * 2 + (e & 1);
                st[b * 128 + a] = acc[mt][nt][e];
            }
    __syncthreads();
    float* dst = g_bpart[blockIdx.x];
#pragma unroll
    for (int i = 0; i < 32; i++)
        dst[i * 512 + t] = st[i * 512 + t];
}

// ---- convM: reduce partials -> U bf16 hi/lo, zero out -------------------------
__global__ void k_convM(float* __restrict__ out, int n_struct) {
    int i = blockIdx.x * blockDim.x + threadIdx.x;   // 65536, i = n*256+a
    if (i < n_struct) out[i] = 0.f;
    int a = i & 255, n = i >> 8;
    float v = 0.f;
    if (a <= n) {
        int tile = (n < 128) ? 0 : ((a < 128) ? 1 : 2);
        int idx = (n & 127) * 128 + (a & 127);
        const float* bp = g_bpart[tile * 64];
#pragma unroll
        for (int s = 0; s < 64; s++) v += bp[(size_t)s * 16384 + idx];
        if (a == n) v *= 0.5f;
    }
    __nv_bfloat16 h = __float2bfloat16(v);
    g_Uhi[i] = h;
    g_Ulo[i] = __float2bfloat16(v - __bfloat162float(h));
}

// ---- quad kernel (unchanged, proven) -------------------------------------------
#define STG    98304
#define QA_HI  0
#define QA_LO  16384
#define QB_HI  32768
#define QB_LO  65536
#define QROW_OFF 196608
#define SMQ_TOTAL 197120

__device__ __forceinline__ void issue_chunk(char* smem, uint32_t sbase,
                                            int stage, int c, int row0,
                                            int n_atoms, int t) {
    const int k0 = c * 64;
    uint32_t abase = sbase + stage * STG;
    char* pbase = smem + stage * STG;
#pragma unroll
    for (int p = 0; p < 2; p++) {
        int g = t + p * 512;
        int row = g >> 3, kq = g & 7;
        uint32_t so = sw_off((uint32_t)(row * 128 + kq * 16));
        if (row0 + row < n_atoms) {
            size_t src = (size_t)(row0 + row) * D_FEAT + k0 + kq * 8;
            cpa16(abase + QA_HI + so, &g_Xhi[src]);
            cpa16(abase + QA_LO + so, &g_Xlo[src]);
        } else {
            uint4 z = make_uint4(0, 0, 0, 0);
            *(uint4*)(pbase + QA_HI + so) = z;
            *(uint4*)(pbase + QA_LO + so) = z;
        }
    }
#pragma unroll
    for (int p = 0; p < 4; p++) {
        int g = t + p * 512;
        int row = g >> 3, kq = g & 7;
        if (row >= c * 64) {
            uint32_t so = sw_off((uint32_t)(row * 128 + kq * 16));
            size_t src = (size_t)row * D_FEAT + k0 + kq * 8;
            cpa16(abase + QB_HI + so, &g_Uhi[src]);
            cpa16(abase + QB_LO + so, &g_Ulo[src]);
        }
    }
}

__global__ void __launch_bounds__(512, 1)
k_quad_mma(const float* __restrict__ X, const int* __restrict__ rowseg,
           float* __restrict__ out, int n_atoms) {
    extern __shared__ char smem[];
    float* qrow = (float*)(smem + QROW_OFF);
    const uint32_t sbase = smem_u32(smem);
    const int t    = threadIdx.x;
    const int lane = t & 31;
    const int w    = t >> 5;
    const int wr   = w & 3;
    const int wc   = w >> 2;
    const int row0 = blockIdx.x * QM;

    if (t < QM) qrow[t] = 0.f;

    float acc[2][8][4];
#pragma unroll
    for (int mt = 0; mt < 2; mt++)
#pragma unroll
        for (int nt = 0; nt < 8; nt++)
#pragma unroll
            for (int e = 0; e < 4; e++) acc[mt][nt][e] = 0.f;

    issue_chunk(smem, sbase, 0, 0, row0, n_atoms, t);
    CP_COMMIT();

#pragma unroll
    for (int c = 0; c < 4; c++) {
        CP_WAIT0();
        __syncthreads();
        if (c < 3) {
            issue_chunk(smem, sbase, (c + 1) & 1, c + 1, row0, n_atoms, t);
            CP_COMMIT();
        }
        if (wc >= c) {
            uint32_t ab = sbase + (c & 1) * STG;
#pragma unroll
            for (int ks = 0; ks < 4; ks++) {
                const int kk = ks * 16;
                uint32_t Ah[2][4], Al[2][4];
                ldsmA(ab + QA_HI, wr * 32 + 0,  kk, lane, Ah[0]);
                ldsmA(ab + QA_HI, wr * 32 + 16, kk, lane, Ah[1]);
                ldsmA(ab + QA_LO, wr * 32 + 0,  kk, lane, Al[0]);
                ldsmA(ab + QA_LO, wr * 32 + 16, kk, lane, Al[1]);
#pragma unroll
                for (int np = 0; np < 4; np++) {
                    uint32_t Bh[4], Bl[4];
                    ldsmB(ab + QB_HI, wc * 64 + np * 16, kk, lane, Bh);
                    ldsmB(ab + QB_LO, wc * 64 + np * 16, kk, lane, Bl);
#pragma unroll
                    for (int mt = 0; mt < 2; mt++) {
#pragma unroll
                        for (int n2 = 0; n2 < 2; n2++) {
                            float* C = acc[mt][np * 2 + n2];
                            mma16816(C, Ah[mt], Bh + n2 * 2);
                            mma16816(C, Ah[mt], Bl + n2 * 2);
                            mma16816(C, Al[mt], Bh + n2 * 2);
                        }
                    }
                }
            }
        }
    }

#pragma unroll
    for (int mt = 0; mt < 2; mt++) {
#pragma unroll
        for (int half = 0; half < 2; half++) {
            int rloc = wr * 32 + mt * 16 + (lane >> 2) + half * 8;
            int rg   = row0 + rloc;
            float qp = 0.f;
            if (rg < n_atoms) {
#pragma unroll
                for (int nt = 0; nt < 8; nt++) {
                    int col = wc * 64 + nt * 8 + (lane & 3) * 2;
                    float2 xv = *(const float2*)&X[(size_t)rg * D_FEAT + col];
                    qp = fmaf(xv.x, acc[mt][nt][half * 2 + 0], qp);
                    qp = fmaf(xv.y, acc[mt][nt][half * 2 + 1], qp);
                }
            }
            qp += __shfl_xor_sync(0xFFFFFFFFu, qp, 1);
            qp += __shfl_xor_sync(0xFFFFFFFFu, qp, 2);
            if ((lane & 3) == 0) atomicAdd(&qrow[rloc], qp);
        }
    }
    __syncthreads();

    if (t < QM) {
        int rg = row0 + t;
        if (rg < n_atoms)
            atomicAdd(&out[rowseg[rg]], 2.0f * qrow[t] * g_rnorm[rg]);
    }
}

// ---- launch --------------------------------------------------------------------
extern "C" void kernel_launch(void* const* d_in, const int* in_sizes, int n_in,
                              void* d_out, int out_size) {
    const float* X      = (const float*)d_in[0];
    const float* S      = (const float*)d_in[1];
    const float* W      = (const float*)d_in[2];
    const int*   rowseg = (const int*)d_in[3];
    const int*   colseg = (const int*)d_in[4];
    float* out = (float*)d_out;

    int n_atoms   = in_sizes[0] / D_FEAT;
    int n_support = in_sizes[1] / D_FEAT;
    int n_struct  = out_size;

    cudaFuncSetAttribute(k_quad_mma, cudaFuncAttributeMaxDynamicSharedMemorySize,
                         SMQ_TOTAL);
    cudaFuncSetAttribute(k_build_mma, cudaFuncAttributeMaxDynamicSharedMemorySize,
                         SMB_TOTAL);

    k_convX<<<(n_atoms + 7) / 8, 256>>>(X, n_atoms);
    k_build_mma<<<192, 512, SMB_TOTAL>>>(S, W, colseg, n_support);
    k_convM<<<D_FEAT * D_FEAT / 256, 256>>>(out, n_struct);
    int gQ = (n_atoms + QM - 1) / QM;
    k_quad_mma<<<gQ, 512, SMQ_TOTAL>>>(X, rowseg, out, n_atoms);
}

// round 7
// speedup vs baseline: 2.7855x; 1.0997x over previous
#include <cuda_runtime.h>
#include <cuda_bf16.h>
#include <cstdint>

// ============================================================================
// FullGap: out[s] = sum_{i in s} (p_i^T M p_i)/(p_i.p_i),
//          M = sum_j w[colseg[j]] s_j s_j^T  (256x256 symmetric)
// x^T M x = 2 x^T U x,  U = strict-upper(M) + diag(M)/2.
// R7: build (HMMA 3-split, reordered MMA passes) -> convM ->
//     quad (inline X conversion, cp.async double-buffered, reordered MMAs,
//           epilogue computes q and |x|^2 together).
// ============================================================================

#define D_FEAT 256
#define QM 128

__device__ float g_bpart[192][16384];                           // 12 MB partials
__device__ __align__(16) __nv_bfloat16 g_Uhi[D_FEAT * D_FEAT];  // [n][a]
__device__ __align__(16) __nv_bfloat16 g_Ulo[D_FEAT * D_FEAT];

// ---------------- helpers ----------------------------------------------------
__device__ __forceinline__ uint32_t smem_u32(const void* p) {
    uint32_t a;
    asm("{ .reg .u64 t; cvta.to.shared.u64 t, %1; cvt.u32.u64 %0, t; }"
        : "=r"(a) : "l"(p));
    return a;
}
__device__ __forceinline__ uint32_t sw_off(uint32_t off) {
    return off ^ ((off >> 3) & 0x70);
}
__device__ __forceinline__ void cpa16(uint32_t dst, const void* src) {
    asm volatile("cp.async.cg.shared.global [%0], [%1], 16;"
                 :: "r"(dst), "l"(__cvta_generic_to_global(src)) : "memory");
}
#define CP_COMMIT() asm volatile("cp.async.commit_group;" ::: "memory")
#define CP_WAIT0()  asm volatile("cp.async.wait_group 0;" ::: "memory")

// non-trans A: smem[m][k] (quad kernel)
__device__ __forceinline__ void ldsmA(uint32_t base, int rb, int kk, int lane,
                                      uint32_t* a) {
    int g = lane >> 3, r = lane & 7;
    int row = rb + r + (g & 1) * 8;
    int col = kk + (g >> 1) * 8;
    uint32_t addr = base + sw_off((uint32_t)(row * 128 + col * 2));
    asm volatile("ldmatrix.sync.aligned.m8n8.x4.shared.b16 {%0,%1,%2,%3}, [%4];"
                 : "=r"(a[0]), "=r"(a[1]), "=r"(a[2]), "=r"(a[3]) : "r"(addr));
}
// non-trans B: smem[n][k] (quad kernel)
__device__ __forceinline__ void ldsmB(uint32_t base, int nb, int kk, int lane,
                                      uint32_t* b) {
    int g = lane >> 3, r = lane & 7;
    int row = nb + r + (g >> 1) * 8;
    int col = kk + (g & 1) * 8;
    uint32_t addr = base + sw_off((uint32_t)(row * 128 + col * 2));
    asm volatile("ldmatrix.sync.aligned.m8n8.x4.shared.b16 {%0,%1,%2,%3}, [%4];"
                 : "=r"(b[0]), "=r"(b[1]), "=r"(b[2]), "=r"(b[3]) : "r"(addr));
}
// trans A: smem[k][m], panels of 128 rows x 64 cols (16 KB)
__device__ __forceinline__ void ldsmT_A(uint32_t base, int ab, int kk, int lane,
                                        uint32_t* a) {
    int g = lane >> 3, r = lane & 7;
    int row = kk + r + (g >> 1) * 8;
    int col = ab + (g & 1) * 8;
    uint32_t addr = base + (uint32_t)(col >> 6) * 16384 +
                    sw_off((uint32_t)(row * 128 + (col & 63) * 2));
    asm volatile("ldmatrix.sync.aligned.m8n8.x4.trans.shared.b16 {%0,%1,%2,%3}, [%4];"
                 : "=r"(a[0]), "=r"(a[1]), "=r"(a[2]), "=r"(a[3]) : "r"(addr));
}
// trans B: smem[k][n], panels of 128 rows x 64 cols
__device__ __forceinline__ void ldsmT_B(uint32_t base, int nb, int kk, int lane,
                                        uint32_t* b) {
    int g = lane >> 3, r = lane & 7;
    int row = kk + r + (g & 1) * 8;
    int col = nb + (g >> 1) * 8;
    uint32_t addr = base + (uint32_t)(col >> 6) * 16384 +
                    sw_off((uint32_t)(row * 128 + (col & 63) * 2));
    asm volatile("ldmatrix.sync.aligned.m8n8.x4.trans.shared.b16 {%0,%1,%2,%3}, [%4];"
                 : "=r"(b[0]), "=r"(b[1]), "=r"(b[2]), "=r"(b[3]) : "r"(addr));
}
__device__ __forceinline__ void mma16816(float* c, const uint32_t* a,
                                         const uint32_t* b) {
    asm volatile(
        "mma.sync.aligned.m16n8k16.row.col.f32.bf16.bf16.f32 "
        "{%0,%1,%2,%3}, {%4,%5,%6,%7}, {%8,%9}, {%0,%1,%2,%3};"
        : "+f"(c[0]), "+f"(c[1]), "+f"(c[2]), "+f"(c[3])
        : "r"(a[0]), "r"(a[1]), "r"(a[2]), "r"(a[3]), "r"(b[0]), "r"(b[1]));
}
__device__ __forceinline__ void bsplit(float x, float y, uint32_t& hi, uint32_t& lo) {
    float hx = __bfloat162float(__float2bfloat16(x));
    float hy = __bfloat162float(__float2bfloat16(y));
    __nv_bfloat162 h = __floats2bfloat162_rn(hx, hy);
    __nv_bfloat162 l = __floats2bfloat162_rn(x - hx, y - hy);
    hi = *(uint32_t*)&h;
    lo = *(uint32_t*)&l;
}

// ---- build: M[a,b] = sum_j S[j][a] * w_j S[j][b], inline conversion -----------
#define BA_HI 0
#define BA_LO 32768
#define BB_HI 65536
#define BB_LO 98304
#define BW_OFF 131072
#define SMB_TOTAL 131584

__global__ void __launch_bounds__(512, 1)
k_build_mma(const float* __restrict__ S, const float* __restrict__ W,
            const int* __restrict__ colseg, int n_support) {
    extern __shared__ char smem[];
    const uint32_t sbase = smem_u32(smem);
    float* sw = (float*)(smem + BW_OFF);
    const int t    = threadIdx.x;
    const int lane = t & 31;
    const int w    = t >> 5;
    const int wr   = w & 3;
    const int wc   = w >> 2;

    const int tile  = blockIdx.x >> 6;
    const int split = blockIdx.x & 63;
    const int a0 = (tile == 2) ? 128 : 0;
    const int b0 = (tile == 0) ? 0 : 128;

    float acc[2][4][4];
#pragma unroll
    for (int mt = 0; mt < 2; mt++)
#pragma unroll
        for (int nt = 0; nt < 4; nt++)
#pragma unroll
            for (int e = 0; e < 4; e++) acc[mt][nt][e] = 0.f;

#pragma unroll 1
    for (int jb = split * 128; jb < n_support; jb += 64 * 128) {
        __syncthreads();
        if (t < 128) {
            int jg = jb + t;
            sw[t] = (jg < n_support) ? W[colseg[jg]] : 0.f;
        }
        __syncthreads();

#pragma unroll
        for (int p = 0; p < 8; p++) {
            int g  = t + p * 512;
            int jl = g >> 5, cq = g & 31;
            int jg = jb + jl;
            float4 v = make_float4(0.f, 0.f, 0.f, 0.f);
            if (jg < n_support)
                v = *(const float4*)&S[(size_t)jg * D_FEAT + a0 + cq * 4];
            uint32_t h0, l0, h1, l1;
            bsplit(v.x, v.y, h0, l0);
            bsplit(v.z, v.w, h1, l1);
            uint32_t off = (uint32_t)(cq >> 4) * 16384 +
                           sw_off((uint32_t)(jl * 128 + (cq & 15) * 8));
            *(uint2*)(smem + BA_HI + off) = make_uint2(h0, h1);
            *(uint2*)(smem + BA_LO + off) = make_uint2(l0, l1);
        }
#pragma unroll
        for (int p = 0; p < 8; p++) {
            int g  = t + p * 512;
            int jl = g >> 5, cq = g & 31;
            int jg = jb + jl;
            float4 v = make_float4(0.f, 0.f, 0.f, 0.f);
            if (jg < n_support)
                v = *(const float4*)&S[(size_t)jg * D_FEAT + b0 + cq * 4];
            float wj = sw[jl];
            uint32_t h0, l0, h1, l1;
            bsplit(wj * v.x, wj * v.y, h0, l0);
            bsplit(wj * v.z, wj * v.w, h1, l1);
            uint32_t off = (uint32_t)(cq >> 4) * 16384 +
                           sw_off((uint32_t)(jl * 128 + (cq & 15) * 8));
            *(uint2*)(smem + BB_HI + off) = make_uint2(h0, h1);
            *(uint2*)(smem + BB_LO + off) = make_uint2(l0, l1);
        }
        __syncthreads();

#pragma unroll
        for (int ks = 0; ks < 8; ks++) {
            const int kk = ks * 16;
            uint32_t Ah[2][4], Al[2][4], Bh[2][4], Bl[2][4];
            ldsmT_A(sbase + BA_HI, wr * 32 + 0,  kk, lane, Ah[0]);
            ldsmT_A(sbase + BA_HI, wr * 32 + 16, kk, lane, Ah[1]);
            ldsmT_A(sbase + BA_LO, wr * 32 + 0,  kk, lane, Al[0]);
            ldsmT_A(sbase + BA_LO, wr * 32 + 16, kk, lane, Al[1]);
            ldsmT_B(sbase + BB_HI, wc * 32 + 0,  kk, lane, Bh[0]);
            ldsmT_B(sbase + BB_HI, wc * 32 + 16, kk, lane, Bh[1]);
            ldsmT_B(sbase + BB_LO, wc * 32 + 0,  kk, lane, Bl[0]);
            ldsmT_B(sbase + BB_LO, wc * 32 + 16, kk, lane, Bl[1]);
            // pass 1: Ah*Bh (8 independent MMAs)
#pragma unroll
            for (int np = 0; np < 2; np++)
#pragma unroll
                for (int mt = 0; mt < 2; mt++)
#pragma unroll
                    for (int n2 = 0; n2 < 2; n2++)
                        mma16816(acc[mt][np * 2 + n2], Ah[mt], Bh[np] + n2 * 2);
            // pass 2: Ah*Bl
#pragma unroll
            for (int np = 0; np < 2; np++)
#pragma unroll
                for (int mt = 0; mt < 2; mt++)
#pragma unroll
                    for (int n2 = 0; n2 < 2; n2++)
                        mma16816(acc[mt][np * 2 + n2], Ah[mt], Bl[np] + n2 * 2);
            // pass 3: Al*Bh
#pragma unroll
            for (int np = 0; np < 2; np++)
#pragma unroll
                for (int mt = 0; mt < 2; mt++)
#pragma unroll
                    for (int n2 = 0; n2 < 2; n2++)
                        mma16816(acc[mt][np * 2 + n2], Al[mt], Bh[np] + n2 * 2);
        }
    }

    __syncthreads();
    float* st = (float*)smem;
#pragma unroll
    for (int mt = 0; mt < 2; mt++)
#pragma unroll
        for (int nt = 0; nt < 4; nt++)
#pragma unroll
            for (int e = 0; e < 4; e++) {
                int a = wr * 32 + mt * 16 + (lane >> 2) + (e >> 1) * 8;
                int b = wc * 32 + nt * 8 + (lane & 3) * 2 + (e & 1);
                st[b * 128 + a] = acc[mt][nt][e];
            }
    __syncthreads();
    float* dst = g_bpart[blockIdx.x];
#pragma unroll
    for (int i = 0; i < 32; i++)
        dst[i * 512 + t] = st[i * 512 + t];
}

// ---- convM: reduce partials -> U bf16 hi/lo, zero out -------------------------
__global__ void k_convM(float* __restrict__ out, int n_struct) {
    int i = blockIdx.x * blockDim.x + threadIdx.x;   // 65536, i = n*256+a
    if (i < n_struct) out[i] = 0.f;
    int a = i & 255, n = i >> 8;
    float v = 0.f;
    if (a <= n) {
        int tile = (n < 128) ? 0 : ((a < 128) ? 1 : 2);
        int idx = (n & 127) * 128 + (a & 127);
        const float* bp = g_bpart[tile * 64];
#pragma unroll
        for (int s = 0; s < 64; s++) v += bp[(size_t)s * 16384 + idx];
        if (a == n) v *= 0.5f;
    }
    __nv_bfloat16 h = __float2bfloat16(v);
    g_Uhi[i] = h;
    g_Ulo[i] = __float2bfloat16(v - __bfloat162float(h));
}

// ---- quad kernel: inline X conversion, double-buffered, reordered MMAs --------
// SMEM: B stage0 hi/lo 64K | B stage1 hi/lo 64K | A-fp32 stage0/1 64K |
//       A-bf16 hi 16K lo 16K | qrow 512 | nnrow 512  = 230400 B
#define QB(s)   ((uint32_t)(s) * 65536u)
#define QBL(s)  ((uint32_t)(s) * 65536u + 32768u)
#define QAF(s)  (131072u + (uint32_t)(s) * 32768u)
#define QAH     196608u
#define QAL     212992u
#define QROW    229376u
#define QNN     229888u
#define SMQ_TOTAL 230400

__device__ __forceinline__ void q_issue(char* smem, const float* X,
                                        const __nv_bfloat16* Uhi,
                                        const __nv_bfloat16* Ulo,
                                        int stage, int c, int row0,
                                        int n_atoms, int t) {
    const int k0 = c * 64;
    // A fp32: 128 rows x 64 cols, linear layout (256 B/row)
#pragma unroll
    for (int p = 0; p < 4; p++) {
        int g = t + p * 512;
        int row = g >> 4, q16 = g & 15;
        uint32_t dst = QAF(stage) + (uint32_t)(row * 256 + q16 * 16);
        if (row0 + row < n_atoms) {
            cpa16(smem_u32(smem) + dst,
                  &X[(size_t)(row0 + row) * D_FEAT + k0 + q16 * 4]);
        } else {
            *(uint4*)(smem + dst) = make_uint4(0, 0, 0, 0);
        }
    }
    // B: 256 rows x 64 cols bf16 hi/lo, SW128; rows < c*64 are zero -> skip
#pragma unroll
    for (int p = 0; p < 4; p++) {
        int g = t + p * 512;
        int row = g >> 3, kq = g & 7;
        if (row >= c * 64) {
            uint32_t so = sw_off((uint32_t)(row * 128 + kq * 16));
            size_t src = (size_t)row * D_FEAT + k0 + kq * 8;
            cpa16(smem_u32(smem) + QB(stage) + so, &Uhi[src]);
            cpa16(smem_u32(smem) + QBL(stage) + so, &Ulo[src]);
        }
    }
}

__global__ void __launch_bounds__(512, 1)
k_quad_mma(const float* __restrict__ X, const int* __restrict__ rowseg,
           float* __restrict__ out, int n_atoms) {
    extern __shared__ char smem[];
    float* qrow  = (float*)(smem + QROW);
    float* nnrow = (float*)(smem + QNN);
    const uint32_t sbase = smem_u32(smem);
    const int t    = threadIdx.x;
    const int lane = t & 31;
    const int w    = t >> 5;
    const int wr   = w & 3;
    const int wc   = w >> 2;
    const int row0 = blockIdx.x * QM;

    if (t < QM) { qrow[t] = 0.f; nnrow[t] = 0.f; }

    float acc[2][8][4];
#pragma unroll
    for (int mt = 0; mt < 2; mt++)
#pragma unroll
        for (int nt = 0; nt < 8; nt++)
#pragma unroll
            for (int e = 0; e < 4; e++) acc[mt][nt][e] = 0.f;

    q_issue(smem, X, g_Uhi, g_Ulo, 0, 0, row0, n_atoms, t);
    CP_COMMIT();

#pragma unroll
    for (int c = 0; c < 4; c++) {
        const int st = c & 1;
        CP_WAIT0();
        __syncthreads();
        if (c < 3) {
            q_issue(smem, X, g_Uhi, g_Ulo, 1 - st, c + 1, row0, n_atoms, t);
            CP_COMMIT();
        }
        // convert A fp32 stage -> bf16 hi/lo (SW128)
#pragma unroll
        for (int p = 0; p < 4; p++) {
            int g = t + p * 512;
            int row = g >> 4, kq = g & 15;
            float4 v = *(const float4*)(smem + QAF(st) + row * 256 + kq * 16);
            uint32_t h0, l0, h1, l1;
            bsplit(v.x, v.y, h0, l0);
            bsplit(v.z, v.w, h1, l1);
            uint32_t so = sw_off((uint32_t)(row * 128 + kq * 8));
            *(uint2*)(smem + QAH + so) = make_uint2(h0, h1);
            *(uint2*)(smem + QAL + so) = make_uint2(l0, l1);
        }
        __syncthreads();

        if (wc >= c) {
#pragma unroll
            for (int ks = 0; ks < 4; ks++) {
                const int kk = ks * 16;
                uint32_t Ah[2][4], Al[2][4];
                ldsmA(sbase + QAH, wr * 32 + 0,  kk, lane, Ah[0]);
                ldsmA(sbase + QAH, wr * 32 + 16, kk, lane, Ah[1]);
                ldsmA(sbase + QAL, wr * 32 + 0,  kk, lane, Al[0]);
                ldsmA(sbase + QAL, wr * 32 + 16, kk, lane, Al[1]);
#pragma unroll
                for (int npp = 0; npp < 2; npp++) {
                    uint32_t Bh[2][4], Bl[2][4];
                    ldsmB(sbase + QB(st),  wc * 64 + npp * 32 + 0,  kk, lane, Bh[0]);
                    ldsmB(sbase + QB(st),  wc * 64 + npp * 32 + 16, kk, lane, Bh[1]);
                    ldsmB(sbase + QBL(st), wc * 64 + npp * 32 + 0,  kk, lane, Bl[0]);
                    ldsmB(sbase + QBL(st), wc * 64 + npp * 32 + 16, kk, lane, Bl[1]);
#pragma unroll
                    for (int np = 0; np < 2; np++)
#pragma unroll
                        for (int mt = 0; mt < 2; mt++)
#pragma unroll
                            for (int n2 = 0; n2 < 2; n2++)
                                mma16816(acc[mt][npp * 4 + np * 2 + n2],
                                         Ah[mt], Bh[np] + n2 * 2);
#pragma unroll
                    for (int np = 0; np < 2; np++)
#pragma unroll
                        for (int mt = 0; mt < 2; mt++)
#pragma unroll
                            for (int n2 = 0; n2 < 2; n2++)
                                mma16816(acc[mt][npp * 4 + np * 2 + n2],
                                         Ah[mt], Bl[np] + n2 * 2);
#pragma unroll
                    for (int np = 0; np < 2; np++)
#pragma unroll
                        for (int mt = 0; mt < 2; mt++)
#pragma unroll
                            for (int n2 = 0; n2 < 2; n2++)
                                mma16816(acc[mt][npp * 4 + np * 2 + n2],
                                         Al[mt], Bh[np] + n2 * 2);
                }
            }
        }
    }

    // ---- epilogue: q = x.y and nn = x.x over this warp's 64-col slice ----
#pragma unroll
    for (int mt = 0; mt < 2; mt++) {
#pragma unroll
        for (int half = 0; half < 2; half++) {
            int rloc = wr * 32 + mt * 16 + (lane >> 2) + half * 8;
            int rg   = row0 + rloc;
            float qp = 0.f, np_ = 0.f;
            if (rg < n_atoms) {
#pragma unroll
                for (int nt = 0; nt < 8; nt++) {
                    int col = wc * 64 + nt * 8 + (lane & 3) * 2;
                    float2 xv = *(const float2*)&X[(size_t)rg * D_FEAT + col];
                    qp  = fmaf(xv.x, acc[mt][nt][half * 2 + 0], qp);
                    qp  = fmaf(xv.y, acc[mt][nt][half * 2 + 1], qp);
                    np_ = fmaf(xv.x, xv.x, np_);
                    np_ = fmaf(xv.y, xv.y, np_);
                }
            }
            qp  += __shfl_xor_sync(0xFFFFFFFFu, qp, 1);
            qp  += __shfl_xor_sync(0xFFFFFFFFu, qp, 2);
            np_ += __shfl_xor_sync(0xFFFFFFFFu, np_, 1);
            np_ += __shfl_xor_sync(0xFFFFFFFFu, np_, 2);
            if ((lane & 3) == 0 && rg < n_atoms) {
                atomicAdd(&qrow[rloc], qp);
                atomicAdd(&nnrow[rloc], np_);
            }
        }
    }
    __syncthreads();

    if (t < QM) {
        int rg = row0 + t;
        if (rg < n_atoms)
            atomicAdd(&out[rowseg[rg]], 2.0f * qrow[t] / nnrow[t]);
    }
}

// ---- launch --------------------------------------------------------------------
extern "C" void kernel_launch(void* const* d_in, const int* in_sizes, int n_in,
                              void* d_out, int out_size) {
    const float* X      = (const float*)d_in[0];
    const float* S      = (const float*)d_in[1];
    const float* W      = (const float*)d_in[2];
    const int*   rowseg = (const int*)d_in[3];
    const int*   colseg = (const int*)d_in[4];
    float* out = (float*)d_out;

    int n_atoms   = in_sizes[0] / D_FEAT;
    int n_support = in_sizes[1] / D_FEAT;
    int n_struct  = out_size;

    cudaFuncSetAttribute(k_quad_mma, cudaFuncAttributeMaxDynamicSharedMemorySize,
                         SMQ_TOTAL);
    cudaFuncSetAttribute(k_build_mma, cudaFuncAttributeMaxDynamicSharedMemorySize,
                         SMB_TOTAL);

    k_build_mma<<<192, 512, SMB_TOTAL>>>(S, W, colseg, n_support);
    k_convM<<<D_FEAT * D_FEAT / 256, 256>>>(out, n_struct);
    int gQ = (n_atoms + QM - 1) / QM;
    k_quad_mma<<<gQ, 512, SMQ_TOTAL>>>(X, rowseg, out, n_atoms);
}

// round 8
// speedup vs baseline: 2.9697x; 1.0661x over previous
#include <cuda_runtime.h>
#include <cuda_bf16.h>
#include <cstdint>

// ============================================================================
// FullGap: out[s] = sum_{i in s} (p_i^T M p_i)/(p_i.p_i),
//          M = sum_j w[colseg[j]] s_j s_j^T  (256x256 symmetric)
// x^T M x = 2 x^T U x,  U = strict-upper(M) + diag(M)/2.
// R8: build (cp.async double-buffered fp32 staging, diagonal-tile load dedup,
//            HMMA 3-split) -> convM -> quad (inline X conversion, striped
//            column ownership for even triangular load balance).
// ============================================================================

#define D_FEAT 256
#define QM 128

__device__ float g_bpart[96][16384];                            // 6 MB partials
__device__ __align__(16) __nv_bfloat16 g_Uhi[D_FEAT * D_FEAT];  // [n][a]
__device__ __align__(16) __nv_bfloat16 g_Ulo[D_FEAT * D_FEAT];

// ---------------- helpers ----------------------------------------------------
__device__ __forceinline__ uint32_t smem_u32(const void* p) {
    uint32_t a;
    asm("{ .reg .u64 t; cvta.to.shared.u64 t, %1; cvt.u32.u64 %0, t; }"
        : "=r"(a) : "l"(p));
    return a;
}
__device__ __forceinline__ uint32_t sw_off(uint32_t off) {
    return off ^ ((off >> 3) & 0x70);
}
__device__ __forceinline__ void cpa16(uint32_t dst, const void* src) {
    asm volatile("cp.async.cg.shared.global [%0], [%1], 16;"
                 :: "r"(dst), "l"(__cvta_generic_to_global(src)) : "memory");
}
#define CP_COMMIT() asm volatile("cp.async.commit_group;" ::: "memory")
#define CP_WAIT(n)  asm volatile("cp.async.wait_group %0;" :: "n"(n) : "memory")

// non-trans A: smem[m][k]
__device__ __forceinline__ void ldsmA(uint32_t base, int rb, int kk, int lane,
                                      uint32_t* a) {
    int g = lane >> 3, r = lane & 7;
    int row = rb + r + (g & 1) * 8;
    int col = kk + (g >> 1) * 8;
    uint32_t addr = base + sw_off((uint32_t)(row * 128 + col * 2));
    asm volatile("ldmatrix.sync.aligned.m8n8.x4.shared.b16 {%0,%1,%2,%3}, [%4];"
                 : "=r"(a[0]), "=r"(a[1]), "=r"(a[2]), "=r"(a[3]) : "r"(addr));
}
// non-trans B: smem[n][k]
__device__ __forceinline__ void ldsmB(uint32_t base, int nb, int kk, int lane,
                                      uint32_t* b) {
    int g = lane >> 3, r = lane & 7;
    int row = nb + r + (g >> 1) * 8;
    int col = kk + (g & 1) * 8;
    uint32_t addr = base + sw_off((uint32_t)(row * 128 + col * 2));
    asm volatile("ldmatrix.sync.aligned.m8n8.x4.shared.b16 {%0,%1,%2,%3}, [%4];"
                 : "=r"(b[0]), "=r"(b[1]), "=r"(b[2]), "=r"(b[3]) : "r"(addr));
}
// trans A: smem[j][m], panels of 64 rows x 64 cols (8 KB)
__device__ __forceinline__ void ldsmT_A(uint32_t base, int ab, int kk, int lane,
                                        uint32_t* a) {
    int g = lane >> 3, r = lane & 7;
    int row = kk + r + (g >> 1) * 8;
    int col = ab + (g & 1) * 8;
    uint32_t addr = base + (uint32_t)(col >> 6) * 8192 +
                    sw_off((uint32_t)(row * 128 + (col & 63) * 2));
    asm volatile("ldmatrix.sync.aligned.m8n8.x4.trans.shared.b16 {%0,%1,%2,%3}, [%4];"
                 : "=r"(a[0]), "=r"(a[1]), "=r"(a[2]), "=r"(a[3]) : "r"(addr));
}
// trans B: smem[j][n], panels of 64 rows x 64 cols
__device__ __forceinline__ void ldsmT_B(uint32_t base, int nb, int kk, int lane,
                                        uint32_t* b) {
    int g = lane >> 3, r = lane & 7;
    int row = kk + r + (g & 1) * 8;
    int col = nb + (g >> 1) * 8;
    uint32_t addr = base + (uint32_t)(col >> 6) * 8192 +
                    sw_off((uint32_t)(row * 128 + (col & 63) * 2));
    asm volatile("ldmatrix.sync.aligned.m8n8.x4.trans.shared.b16 {%0,%1,%2,%3}, [%4];"
                 : "=r"(b[0]), "=r"(b[1]), "=r"(b[2]), "=r"(b[3]) : "r"(addr));
}
__device__ __forceinline__ void mma16816(float* c, const uint32_t* a,
                                         const uint32_t* b) {
    asm volatile(
        "mma.sync.aligned.m16n8k16.row.col.f32.bf16.bf16.f32 "
        "{%0,%1,%2,%3}, {%4,%5,%6,%7}, {%8,%9}, {%0,%1,%2,%3};"
        : "+f"(c[0]), "+f"(c[1]), "+f"(c[2]), "+f"(c[3])
        : "r"(a[0]), "r"(a[1]), "r"(a[2]), "r"(a[3]), "r"(b[0]), "r"(b[1]));
}
__device__ __forceinline__ void bsplit(float x, float y, uint32_t& hi, uint32_t& lo) {
    float hx = __bfloat162float(__float2bfloat16(x));
    float hy = __bfloat162float(__float2bfloat16(y));
    __nv_bfloat162 h = __floats2bfloat162_rn(hx, hy);
    __nv_bfloat162 l = __floats2bfloat162_rn(x - hx, y - hy);
    hi = *(uint32_t*)&h;
    lo = *(uint32_t*)&l;
}

// ---- build: M[a,b] = sum_j S[j][a] * w_j S[j][b] ------------------------------
// 96 CTAs = 3 tiles x 32 splits. 256 j per CTA, 4 chunks of 64, double-buffered.
// SMEM: FA fp32 32K x2 | FB fp32 32K x2 | AH/AL/BH/BL bf16 16K each | w 1K
#define FB_A(s) ((uint32_t)(s) * 32768u)
#define FB_B(s) (65536u + (uint32_t)(s) * 32768u)
#define BAH 131072u
#define BAL 147456u
#define BBH 163840u
#define BBL 180224u
#define BWO 196608u
#define SMB_TOTAL 197632

__device__ __forceinline__ void b_issue(char* smem, uint32_t sbase,
                                        const float* S, int stage, int jb,
                                        int a0, int b0, bool same,
                                        int n_support, int t) {
#pragma unroll
    for (int p = 0; p < 4; p++) {
        int g = t + p * 512;          // 2048 granules = 64 j x 32 float4
        int jl = g >> 5, cq = g & 31;
        int jg = jb + jl;
        uint32_t dst = FB_A(stage) + (uint32_t)(jl * 512 + cq * 16);
        if (jg < n_support)
            cpa16(sbase + dst, &S[(size_t)jg * D_FEAT + a0 + cq * 4]);
        else
            *(uint4*)(smem + dst) = make_uint4(0, 0, 0, 0);
    }
    if (!same) {
#pragma unroll
        for (int p = 0; p < 4; p++) {
            int g = t + p * 512;
            int jl = g >> 5, cq = g & 31;
            int jg = jb + jl;
            uint32_t dst = FB_B(stage) + (uint32_t)(jl * 512 + cq * 16);
            if (jg < n_support)
                cpa16(sbase + dst, &S[(size_t)jg * D_FEAT + b0 + cq * 4]);
            else
                *(uint4*)(smem + dst) = make_uint4(0, 0, 0, 0);
        }
    }
}

__global__ void __launch_bounds__(512, 1)
k_build_mma(const float* __restrict__ S, const float* __restrict__ W,
            const int* __restrict__ colseg, int n_support) {
    extern __shared__ char smem[];
    const uint32_t sbase = smem_u32(smem);
    float* wsm = (float*)(smem + BWO);
    const int t    = threadIdx.x;
    const int lane = t & 31;
    const int w    = t >> 5;
    const int wr   = w & 3;
    const int wc   = w >> 2;

    const int tile  = blockIdx.x >> 5;
    const int split = blockIdx.x & 31;
    const int a0 = (tile == 2) ? 128 : 0;
    const int b0 = (tile == 0) ? 0 : 128;
    const bool same = (a0 == b0);
    const int jorg = split * 256;

    if (t < 256) {
        int jg = jorg + t;
        wsm[t] = (jg < n_support) ? W[colseg[jg]] : 0.f;
    }

    b_issue(smem, sbase, S, 0, jorg, a0, b0, same, n_support, t);
    CP_COMMIT();

    float acc[2][4][4];
#pragma unroll
    for (int mt = 0; mt < 2; mt++)
#pragma unroll
        for (int nt = 0; nt < 4; nt++)
#pragma unroll
            for (int e = 0; e < 4; e++) acc[mt][nt][e] = 0.f;

#pragma unroll 1
    for (int c = 0; c < 4; c++) {
        const int st = c & 1;
        if (c < 3) {
            b_issue(smem, sbase, S, 1 - st, jorg + (c + 1) * 64, a0, b0, same,
                    n_support, t);
            CP_COMMIT();
            CP_WAIT(1);
        } else {
            CP_WAIT(0);
        }
        __syncthreads();   // loads of chunk c visible; prior MMA done

        // convert A: fp32 -> bf16 hi/lo trans panels
#pragma unroll
        for (int p = 0; p < 4; p++) {
            int g = t + p * 512;
            int jl = g >> 5, cq = g & 31;
            float4 v = *(const float4*)(smem + FB_A(st) + jl * 512 + cq * 16);
            uint32_t h0, l0, h1, l1;
            bsplit(v.x, v.y, h0, l0);
            bsplit(v.z, v.w, h1, l1);
            uint32_t off = (uint32_t)(cq >> 4) * 8192 +
                           sw_off((uint32_t)(jl * 128 + (cq & 15) * 8));
            *(uint2*)(smem + BAH + off) = make_uint2(h0, h1);
            *(uint2*)(smem + BAL + off) = make_uint2(l0, l1);
        }
        // convert B: w_j * fp32 -> bf16 hi/lo
#pragma unroll
        for (int p = 0; p < 4; p++) {
            int g = t + p * 512;
            int jl = g >> 5, cq = g & 31;
            uint32_t src = (same ? FB_A(st) : FB_B(st)) + (uint32_t)(jl * 512 + cq * 16);
            float4 v = *(const float4*)(smem + src);
            float wj = wsm[c * 64 + jl];
            uint32_t h0, l0, h1, l1;
            bsplit(wj * v.x, wj * v.y, h0, l0);
            bsplit(wj * v.z, wj * v.w, h1, l1);
            uint32_t off = (uint32_t)(cq >> 4) * 8192 +
                           sw_off((uint32_t)(jl * 128 + (cq & 15) * 8));
            *(uint2*)(smem + BBH + off) = make_uint2(h0, h1);
            *(uint2*)(smem + BBL + off) = make_uint2(l0, l1);
        }
        __syncthreads();

#pragma unroll
        for (int ks = 0; ks < 4; ks++) {
            const int kk = ks * 16;
            uint32_t Ah[2][4], Al[2][4], Bh[2][4], Bl[2][4];
            ldsmT_A(sbase + BAH, wr * 32 + 0,  kk, lane, Ah[0]);
            ldsmT_A(sbase + BAH, wr * 32 + 16, kk, lane, Ah[1]);
            ldsmT_A(sbase + BAL, wr * 32 + 0,  kk, lane, Al[0]);
            ldsmT_A(sbase + BAL, wr * 32 + 16, kk, lane, Al[1]);
            ldsmT_B(sbase + BBH, wc * 32 + 0,  kk, lane, Bh[0]);
            ldsmT_B(sbase + BBH, wc * 32 + 16, kk, lane, Bh[1]);
            ldsmT_B(sbase + BBL, wc * 32 + 0,  kk, lane, Bl[0]);
            ldsmT_B(sbase + BBL, wc * 32 + 16, kk, lane, Bl[1]);
#pragma unroll
            for (int np = 0; np < 2; np++)
#pragma unroll
                for (int mt = 0; mt < 2; mt++)
#pragma unroll
                    for (int n2 = 0; n2 < 2; n2++)
                        mma16816(acc[mt][np * 2 + n2], Ah[mt], Bh[np] + n2 * 2);
#pragma unroll
            for (int np = 0; np < 2; np++)
#pragma unroll
                for (int mt = 0; mt < 2; mt++)
#pragma unroll
                    for (int n2 = 0; n2 < 2; n2++)
                        mma16816(acc[mt][np * 2 + n2], Ah[mt], Bl[np] + n2 * 2);
#pragma unroll
            for (int np = 0; np < 2; np++)
#pragma unroll
                for (int mt = 0; mt < 2; mt++)
#pragma unroll
                    for (int n2 = 0; n2 < 2; n2++)
                        mma16816(acc[mt][np * 2 + n2], Al[mt], Bh[np] + n2 * 2);
        }
    }

    __syncthreads();
    float* stg = (float*)smem;
#pragma unroll
    for (int mt = 0; mt < 2; mt++)
#pragma unroll
        for (int nt = 0; nt < 4; nt++)
#pragma unroll
            for (int e = 0; e < 4; e++) {
                int a = wr * 32 + mt * 16 + (lane >> 2) + (e >> 1) * 8;
                int b = wc * 32 + nt * 8 + (lane & 3) * 2 + (e & 1);
                stg[b * 128 + a] = acc[mt][nt][e];
            }
    __syncthreads();
    float* dst = g_bpart[blockIdx.x];
#pragma unroll
    for (int i = 0; i < 32; i++)
        dst[i * 512 + t] = stg[i * 512 + t];
}

// ---- convM: reduce partials -> U bf16 hi/lo, zero out -------------------------
__global__ void k_convM(float* __restrict__ out, int n_struct) {
    int i = blockIdx.x * blockDim.x + threadIdx.x;   // 65536, i = n*256+a
    if (i < n_struct) out[i] = 0.f;
    int a = i & 255, n = i >> 8;
    float v = 0.f;
    if (a <= n) {
        int tile = (n < 128) ? 0 : ((a < 128) ? 1 : 2);
        int idx = (n & 127) * 128 + (a & 127);
        const float* bp = g_bpart[tile * 32];
#pragma unroll
        for (int s = 0; s < 32; s++) v += bp[(size_t)s * 16384 + idx];
        if (a == n) v *= 0.5f;
    }
    __nv_bfloat16 h = __float2bfloat16(v);
    g_Uhi[i] = h;
    g_Ulo[i] = __float2bfloat16(v - __bfloat162float(h));
}

// ---- quad kernel: striped columns, inline X conversion ------------------------
#define QB(s)   ((uint32_t)(s) * 65536u)
#define QBL(s)  ((uint32_t)(s) * 65536u + 32768u)
#define QAF(s)  (131072u + (uint32_t)(s) * 32768u)
#define QAH     196608u
#define QAL     212992u
#define QROW    229376u
#define QNN     229888u
#define SMQ_TOTAL 230400

__device__ __forceinline__ void q_issue(char* smem, const float* X,
                                        const __nv_bfloat16* Uhi,
                                        const __nv_bfloat16* Ulo,
                                        int stage, int c, int row0,
                                        int n_atoms, int t) {
    const int k0 = c * 64;
#pragma unroll
    for (int p = 0; p < 4; p++) {
        int g = t + p * 512;
        int row = g >> 4, q16 = g & 15;
        uint32_t dst = QAF(stage) + (uint32_t)(row * 256 + q16 * 16);
        if (row0 + row < n_atoms) {
            cpa16(smem_u32(smem) + dst,
                  &X[(size_t)(row0 + row) * D_FEAT + k0 + q16 * 4]);
        } else {
            *(uint4*)(smem + dst) = make_uint4(0, 0, 0, 0);
        }
    }
#pragma unroll
    for (int p = 0; p < 4; p++) {
        int g = t + p * 512;
        int row = g >> 3, kq = g & 7;
        if (row >= c * 64) {
            uint32_t so = sw_off((uint32_t)(row * 128 + kq * 16));
            size_t src = (size_t)row * D_FEAT + k0 + kq * 8;
            cpa16(smem_u32(smem) + QB(stage) + so, &Uhi[src]);
            cpa16(smem_u32(smem) + QBL(stage) + so, &Ulo[src]);
        }
    }
}

__global__ void __launch_bounds__(512, 1)
k_quad_mma(const float* __restrict__ X, const int* __restrict__ rowseg,
           float* __restrict__ out, int n_atoms) {
    extern __shared__ char smem[];
    float* qrow  = (float*)(smem + QROW);
    float* nnrow = (float*)(smem + QNN);
    const uint32_t sbase = smem_u32(smem);
    const int t    = threadIdx.x;
    const int lane = t & 31;
    const int w    = t >> 5;
    const int wr   = w & 3;
    const int wc   = w >> 2;
    const int row0 = blockIdx.x * QM;

    if (t < QM) { qrow[t] = 0.f; nnrow[t] = 0.f; }

    // acc[mt][i*2+n2]: stripe i covers cols i*64 + wc*16 .. +16
    float acc[2][8][4];
#pragma unroll
    for (int mt = 0; mt < 2; mt++)
#pragma unroll
        for (int nt = 0; nt < 8; nt++)
#pragma unroll
            for (int e = 0; e < 4; e++) acc[mt][nt][e] = 0.f;

    q_issue(smem, X, g_Uhi, g_Ulo, 0, 0, row0, n_atoms, t);
    CP_COMMIT();

#pragma unroll
    for (int c = 0; c < 4; c++) {
        const int st = c & 1;
        CP_WAIT(0);
        __syncthreads();
        if (c < 3) {
            q_issue(smem, X, g_Uhi, g_Ulo, 1 - st, c + 1, row0, n_atoms, t);
            CP_COMMIT();
        }
        // convert A fp32 stage -> bf16 hi/lo (SW128)
#pragma unroll
        for (int p = 0; p < 4; p++) {
            int g = t + p * 512;
            int row = g >> 4, kq = g & 15;
            float4 v = *(const float4*)(smem + QAF(st) + row * 256 + kq * 16);
            uint32_t h0, l0, h1, l1;
            bsplit(v.x, v.y, h0, l0);
            bsplit(v.z, v.w, h1, l1);
            uint32_t so = sw_off((uint32_t)(row * 128 + kq * 8));
            *(uint2*)(smem + QAH + so) = make_uint2(h0, h1);
            *(uint2*)(smem + QAL + so) = make_uint2(l0, l1);
        }
        __syncthreads();

#pragma unroll
        for (int ks = 0; ks < 4; ks++) {
            const int kk = ks * 16;
            uint32_t Ah[2][4], Al[2][4];
            ldsmA(sbase + QAH, wr * 32 + 0,  kk, lane, Ah[0]);
            ldsmA(sbase + QAH, wr * 32 + 16, kk, lane, Ah[1]);
            ldsmA(sbase + QAL, wr * 32 + 0,  kk, lane, Al[0]);
            ldsmA(sbase + QAL, wr * 32 + 16, kk, lane, Al[1]);
#pragma unroll
            for (int i = 0; i < 4; i++) {
                if (i < c) continue;              // c is compile-time (unrolled)
                uint32_t Bh[4], Bl[4];
                ldsmB(sbase + QB(st),  i * 64 + wc * 16, kk, lane, Bh);
                ldsmB(sbase + QBL(st), i * 64 + wc * 16, kk, lane, Bl);
#pragma unroll
                for (int mt = 0; mt < 2; mt++)
#pragma unroll
                    for (int n2 = 0; n2 < 2; n2++)
                        mma16816(acc[mt][i * 2 + n2], Ah[mt], Bh + n2 * 2);
#pragma unroll
                for (int mt = 0; mt < 2; mt++)
#pragma unroll
                    for (int n2 = 0; n2 < 2; n2++)
                        mma16816(acc[mt][i * 2 + n2], Ah[mt], Bl + n2 * 2);
#pragma unroll
                for (int mt = 0; mt < 2; mt++)
#pragma unroll
                    for (int n2 = 0; n2 < 2; n2++)
                        mma16816(acc[mt][i * 2 + n2], Al[mt], Bh + n2 * 2);
            }
        }
    }

    // ---- epilogue: q = x.y and nn = x.x over this warp's striped cols ----
#pragma unroll
    for (int mt = 0; mt < 2; mt++) {
#pragma unroll
        for (int half = 0; half < 2; half++) {
            int rloc = wr * 32 + mt * 16 + (lane >> 2) + half * 8;
            int rg   = row0 + rloc;
            float qp = 0.f, np_ = 0.f;
            if (rg < n_atoms) {
#pragma unroll
                for (int i = 0; i < 4; i++) {
#pragma unroll
                    for (int n2 = 0; n2 < 2; n2++) {
                        int col = i * 64 + wc * 16 + n2 * 8 + (lane & 3) * 2;
                        float2 xv = *(const float2*)&X[(size_t)rg * D_FEAT + col];
                        qp  = fmaf(xv.x, acc[mt][i * 2 + n2][half * 2 + 0], qp);
                        qp  = fmaf(xv.y, acc[mt][i * 2 + n2][half * 2 + 1], qp);
                        np_ = fmaf(xv.x, xv.x, np_);
                        np_ = fmaf(xv.y, xv.y, np_);
                    }
                }
            }
            qp  += __shfl_xor_sync(0xFFFFFFFFu, qp, 1);
            qp  += __shfl_xor_sync(0xFFFFFFFFu, qp, 2);
            np_ += __shfl_xor_sync(0xFFFFFFFFu, np_, 1);
            np_ += __shfl_xor_sync(0xFFFFFFFFu, np_, 2);
            if ((lane & 3) == 0 && rg < n_atoms) {
                atomicAdd(&qrow[rloc], qp);
                atomicAdd(&nnrow[rloc], np_);
            }
        }
    }
    __syncthreads();

    if (t < QM) {
        int rg = row0 + t;
        if (rg < n_atoms)
            atomicAdd(&out[rowseg[rg]], 2.0f * qrow[t] / nnrow[t]);
    }
}

// ---- launch --------------------------------------------------------------------
extern "C" void kernel_launch(void* const* d_in, const int* in_sizes, int n_in,
                              void* d_out, int out_size) {
    const float* X      = (const float*)d_in[0];
    const float* S      = (const float*)d_in[1];
    const float* W      = (const float*)d_in[2];
    const int*   rowseg = (const int*)d_in[3];
    const int*   colseg = (const int*)d_in[4];
    float* out = (float*)d_out;

    int n_atoms   = in_sizes[0] / D_FEAT;
    int n_support = in_sizes[1] / D_FEAT;
    int n_struct  = out_size;

    cudaFuncSetAttribute(k_quad_mma, cudaFuncAttributeMaxDynamicSharedMemorySize,
                         SMQ_TOTAL);
    cudaFuncSetAttribute(k_build_mma, cudaFuncAttributeMaxDynamicSharedMemorySize,
                         SMB_TOTAL);

    k_build_mma<<<96, 512, SMB_TOTAL>>>(S, W, colseg, n_support);
    k_convM<<<D_FEAT * D_FEAT / 256, 256>>>(out, n_struct);
    int gQ = (n_atoms + QM - 1) / QM;
    k_quad_mma<<<gQ, 512, SMQ_TOTAL>>>(X, rowseg, out, n_atoms);
}

// round 9
// speedup vs baseline: 3.0977x; 1.0431x over previous
#include <cuda_runtime.h>
#include <cuda_bf16.h>
#include <cstdint>

// ============================================================================
// FullGap: out[s] = sum_{i in s} (p_i^T M p_i)/(p_i.p_i),
//          M = sum_j w[colseg[j]] s_j s_j^T  (256x256 symmetric)
// x^T M x = 2 x^T U x,  U = strict-upper(M) + diag(M)/2.
// R9: build (grid 129 = full wave, cp.async double-buffered, HMMA 3-split)
//     -> convM -> quad (striped cols, inline X conversion, SMEM-Y epilogue
//     with coalesced X re-read).
// ============================================================================

#define D_FEAT 256
#define QM 128
#define NSPL 43    // splits per tile; 43*192 = 8256 >= 8192

__device__ float g_bpart[3 * NSPL][16384];                      // 8.4 MB partials
__device__ __align__(16) __nv_bfloat16 g_Uhi[D_FEAT * D_FEAT];  // [n][a]
__device__ __align__(16) __nv_bfloat16 g_Ulo[D_FEAT * D_FEAT];

// ---------------- helpers ----------------------------------------------------
__device__ __forceinline__ uint32_t smem_u32(const void* p) {
    uint32_t a;
    asm("{ .reg .u64 t; cvta.to.shared.u64 t, %1; cvt.u32.u64 %0, t; }"
        : "=r"(a) : "l"(p));
    return a;
}
__device__ __forceinline__ uint32_t sw_off(uint32_t off) {
    return off ^ ((off >> 3) & 0x70);
}
__device__ __forceinline__ void cpa16(uint32_t dst, const void* src) {
    asm volatile("cp.async.cg.shared.global [%0], [%1], 16;"
                 :: "r"(dst), "l"(__cvta_generic_to_global(src)) : "memory");
}
#define CP_COMMIT() asm volatile("cp.async.commit_group;" ::: "memory")
#define CP_WAIT(n)  asm volatile("cp.async.wait_group %0;" :: "n"(n) : "memory")

// non-trans A: smem[m][k]
__device__ __forceinline__ void ldsmA(uint32_t base, int rb, int kk, int lane,
                                      uint32_t* a) {
    int g = lane >> 3, r = lane & 7;
    int row = rb + r + (g & 1) * 8;
    int col = kk + (g >> 1) * 8;
    uint32_t addr = base + sw_off((uint32_t)(row * 128 + col * 2));
    asm volatile("ldmatrix.sync.aligned.m8n8.x4.shared.b16 {%0,%1,%2,%3}, [%4];"
                 : "=r"(a[0]), "=r"(a[1]), "=r"(a[2]), "=r"(a[3]) : "r"(addr));
}
// non-trans B: smem[n][k]
__device__ __forceinline__ void ldsmB(uint32_t base, int nb, int kk, int lane,
                                      uint32_t* b) {
    int g = lane >> 3, r = lane & 7;
    int row = nb + r + (g >> 1) * 8;
    int col = kk + (g & 1) * 8;
    uint32_t addr = base + sw_off((uint32_t)(row * 128 + col * 2));
    asm volatile("ldmatrix.sync.aligned.m8n8.x4.shared.b16 {%0,%1,%2,%3}, [%4];"
                 : "=r"(b[0]), "=r"(b[1]), "=r"(b[2]), "=r"(b[3]) : "r"(addr));
}
// trans A: smem[j][m], panels of 64 rows x 64 cols (8 KB)
__device__ __forceinline__ void ldsmT_A(uint32_t base, int ab, int kk, int lane,
                                        uint32_t* a) {
    int g = lane >> 3, r = lane & 7;
    int row = kk + r + (g >> 1) * 8;
    int col = ab + (g & 1) * 8;
    uint32_t addr = base + (uint32_t)(col >> 6) * 8192 +
                    sw_off((uint32_t)(row * 128 + (col & 63) * 2));
    asm volatile("ldmatrix.sync.aligned.m8n8.x4.trans.shared.b16 {%0,%1,%2,%3}, [%4];"
                 : "=r"(a[0]), "=r"(a[1]), "=r"(a[2]), "=r"(a[3]) : "r"(addr));
}
// trans B: smem[j][n]
__device__ __forceinline__ void ldsmT_B(uint32_t base, int nb, int kk, int lane,
                                        uint32_t* b) {
    int g = lane >> 3, r = lane & 7;
    int row = kk + r + (g & 1) * 8;
    int col = nb + (g >> 1) * 8;
    uint32_t addr = base + (uint32_t)(col >> 6) * 8192 +
                    sw_off((uint32_t)(row * 128 + (col & 63) * 2));
    asm volatile("ldmatrix.sync.aligned.m8n8.x4.trans.shared.b16 {%0,%1,%2,%3}, [%4];"
                 : "=r"(b[0]), "=r"(b[1]), "=r"(b[2]), "=r"(b[3]) : "r"(addr));
}
__device__ __forceinline__ void mma16816(float* c, const uint32_t* a,
                                         const uint32_t* b) {
    asm volatile(
        "mma.sync.aligned.m16n8k16.row.col.f32.bf16.bf16.f32 "
        "{%0,%1,%2,%3}, {%4,%5,%6,%7}, {%8,%9}, {%0,%1,%2,%3};"
        : "+f"(c[0]), "+f"(c[1]), "+f"(c[2]), "+f"(c[3])
        : "r"(a[0]), "r"(a[1]), "r"(a[2]), "r"(a[3]), "r"(b[0]), "r"(b[1]));
}
__device__ __forceinline__ void bsplit(float x, float y, uint32_t& hi, uint32_t& lo) {
    float hx = __bfloat162float(__float2bfloat16(x));
    float hy = __bfloat162float(__float2bfloat16(y));
    __nv_bfloat162 h = __floats2bfloat162_rn(hx, hy);
    __nv_bfloat162 l = __floats2bfloat162_rn(x - hx, y - hy);
    hi = *(uint32_t*)&h;
    lo = *(uint32_t*)&l;
}

// ---- build: M[a,b] = sum_j S[j][a] * w_j S[j][b] ------------------------------
// 129 CTAs = 3 tiles x 43 splits. 192 j per CTA, 3 chunks of 64, double-buffered.
#define FB_A(s) ((uint32_t)(s) * 32768u)
#define FB_B(s) (65536u + (uint32_t)(s) * 32768u)
#define BAH 131072u
#define BAL 147456u
#define BBH 163840u
#define BBL 180224u
#define BWO 196608u
#define SMB_TOTAL 197632

__device__ __forceinline__ void b_issue(char* smem, uint32_t sbase,
                                        const float* S, int stage, int jb,
                                        int a0, int b0, bool same,
                                        int n_support, int t) {
#pragma unroll
    for (int p = 0; p < 4; p++) {
        int g = t + p * 512;          // 2048 granules = 64 j x 32 float4
        int jl = g >> 5, cq = g & 31;
        int jg = jb + jl;
        uint32_t dst = FB_A(stage) + (uint32_t)(jl * 512 + cq * 16);
        if (jg < n_support)
            cpa16(sbase + dst, &S[(size_t)jg * D_FEAT + a0 + cq * 4]);
        else
            *(uint4*)(smem + dst) = make_uint4(0, 0, 0, 0);
    }
    if (!same) {
#pragma unroll
        for (int p = 0; p < 4; p++) {
            int g = t + p * 512;
            int jl = g >> 5, cq = g & 31;
            int jg = jb + jl;
            uint32_t dst = FB_B(stage) + (uint32_t)(jl * 512 + cq * 16);
            if (jg < n_support)
                cpa16(sbase + dst, &S[(size_t)jg * D_FEAT + b0 + cq * 4]);
            else
                *(uint4*)(smem + dst) = make_uint4(0, 0, 0, 0);
        }
    }
}

__global__ void __launch_bounds__(512, 1)
k_build_mma(const float* __restrict__ S, const float* __restrict__ W,
            const int* __restrict__ colseg, int n_support) {
    extern __shared__ char smem[];
    const uint32_t sbase = smem_u32(smem);
    float* wsm = (float*)(smem + BWO);
    const int t    = threadIdx.x;
    const int lane = t & 31;
    const int w    = t >> 5;
    const int wr   = w & 3;
    const int wc   = w >> 2;

    const int tile  = blockIdx.x / NSPL;
    const int split = blockIdx.x % NSPL;
    const int a0 = (tile == 2) ? 128 : 0;
    const int b0 = (tile == 0) ? 0 : 128;
    const bool same = (a0 == b0);
    const int jorg = split * 192;

    if (t < 192) {
        int jg = jorg + t;
        wsm[t] = (jg < n_support) ? W[colseg[jg]] : 0.f;
    }

    b_issue(smem, sbase, S, 0, jorg, a0, b0, same, n_support, t);
    CP_COMMIT();

    float acc[2][4][4];
#pragma unroll
    for (int mt = 0; mt < 2; mt++)
#pragma unroll
        for (int nt = 0; nt < 4; nt++)
#pragma unroll
            for (int e = 0; e < 4; e++) acc[mt][nt][e] = 0.f;

#pragma unroll 1
    for (int c = 0; c < 3; c++) {
        const int st = c & 1;
        if (c < 2) {
            b_issue(smem, sbase, S, 1 - st, jorg + (c + 1) * 64, a0, b0, same,
                    n_support, t);
            CP_COMMIT();
            CP_WAIT(1);
        } else {
            CP_WAIT(0);
        }
        __syncthreads();

        // convert A: fp32 -> bf16 hi/lo trans panels
#pragma unroll
        for (int p = 0; p < 4; p++) {
            int g = t + p * 512;
            int jl = g >> 5, cq = g & 31;
            float4 v = *(const float4*)(smem + FB_A(st) + jl * 512 + cq * 16);
            uint32_t h0, l0, h1, l1;
            bsplit(v.x, v.y, h0, l0);
            bsplit(v.z, v.w, h1, l1);
            uint32_t off = (uint32_t)(cq >> 4) * 8192 +
                           sw_off((uint32_t)(jl * 128 + (cq & 15) * 8));
            *(uint2*)(smem + BAH + off) = make_uint2(h0, h1);
            *(uint2*)(smem + BAL + off) = make_uint2(l0, l1);
        }
        // convert B: w_j * fp32 -> bf16 hi/lo
#pragma unroll
        for (int p = 0; p < 4; p++) {
            int g = t + p * 512;
            int jl = g >> 5, cq = g & 31;
            uint32_t src = (same ? FB_A(st) : FB_B(st)) + (uint32_t)(jl * 512 + cq * 16);
            float4 v = *(const float4*)(smem + src);
            float wj = wsm[c * 64 + jl];
            uint32_t h0, l0, h1, l1;
            bsplit(wj * v.x, wj * v.y, h0, l0);
            bsplit(wj * v.z, wj * v.w, h1, l1);
            uint32_t off = (uint32_t)(cq >> 4) * 8192 +
                           sw_off((uint32_t)(jl * 128 + (cq & 15) * 8));
            *(uint2*)(smem + BBH + off) = make_uint2(h0, h1);
            *(uint2*)(smem + BBL + off) = make_uint2(l0, l1);
        }
        __syncthreads();

#pragma unroll
        for (int ks = 0; ks < 4; ks++) {
            const int kk = ks * 16;
            uint32_t Ah[2][4], Al[2][4], Bh[2][4], Bl[2][4];
            ldsmT_A(sbase + BAH, wr * 32 + 0,  kk, lane, Ah[0]);
            ldsmT_A(sbase + BAH, wr * 32 + 16, kk, lane, Ah[1]);
            ldsmT_A(sbase + BAL, wr * 32 + 0,  kk, lane, Al[0]);
            ldsmT_A(sbase + BAL, wr * 32 + 16, kk, lane, Al[1]);
            ldsmT_B(sbase + BBH, wc * 32 + 0,  kk, lane, Bh[0]);
            ldsmT_B(sbase + BBH, wc * 32 + 16, kk, lane, Bh[1]);
            ldsmT_B(sbase + BBL, wc * 32 + 0,  kk, lane, Bl[0]);
            ldsmT_B(sbase + BBL, wc * 32 + 16, kk, lane, Bl[1]);
#pragma unroll
            for (int np = 0; np < 2; np++)
#pragma unroll
                for (int mt = 0; mt < 2; mt++)
#pragma unroll
                    for (int n2 = 0; n2 < 2; n2++)
                        mma16816(acc[mt][np * 2 + n2], Ah[mt], Bh[np] + n2 * 2);
#pragma unroll
            for (int np = 0; np < 2; np++)
#pragma unroll
                for (int mt = 0; mt < 2; mt++)
#pragma unroll
                    for (int n2 = 0; n2 < 2; n2++)
                        mma16816(acc[mt][np * 2 + n2], Ah[mt], Bl[np] + n2 * 2);
#pragma unroll
            for (int np = 0; np < 2; np++)
#pragma unroll
                for (int mt = 0; mt < 2; mt++)
#pragma unroll
                    for (int n2 = 0; n2 < 2; n2++)
                        mma16816(acc[mt][np * 2 + n2], Al[mt], Bh[np] + n2 * 2);
        }
    }

    __syncthreads();
    float* stg = (float*)smem;
#pragma unroll
    for (int mt = 0; mt < 2; mt++)
#pragma unroll
        for (int nt = 0; nt < 4; nt++)
#pragma unroll
            for (int e = 0; e < 4; e++) {
                int a = wr * 32 + mt * 16 + (lane >> 2) + (e >> 1) * 8;
                int b = wc * 32 + nt * 8 + (lane & 3) * 2 + (e & 1);
                stg[b * 128 + a] = acc[mt][nt][e];
            }
    __syncthreads();
    float* dst = g_bpart[blockIdx.x];
#pragma unroll
    for (int i = 0; i < 32; i++)
        dst[i * 512 + t] = stg[i * 512 + t];
}

// ---- convM: reduce partials -> U bf16 hi/lo, zero out -------------------------
__global__ void k_convM(float* __restrict__ out, int n_struct) {
    int i = blockIdx.x * blockDim.x + threadIdx.x;   // 65536, i = n*256+a
    if (i < n_struct) out[i] = 0.f;
    int a = i & 255, n = i >> 8;
    float v = 0.f;
    if (a <= n) {
        int tile = (n < 128) ? 0 : ((a < 128) ? 1 : 2);
        int idx = (n & 127) * 128 + (a & 127);
        const float* bp = g_bpart[tile * NSPL];
#pragma unroll
        for (int s = 0; s < NSPL; s++) v += bp[(size_t)s * 16384 + idx];
        if (a == n) v *= 0.5f;
    }
    __nv_bfloat16 h = __float2bfloat16(v);
    g_Uhi[i] = h;
    g_Ulo[i] = __float2bfloat16(v - __bfloat162float(h));
}

// ---- quad kernel: striped columns, inline X conversion, SMEM-Y epilogue -------
#define QB(s)   ((uint32_t)(s) * 65536u)
#define QBL(s)  ((uint32_t)(s) * 65536u + 32768u)
#define QAF(s)  (131072u + (uint32_t)(s) * 32768u)
#define QAH     196608u
#define QAL     212992u
#define SMQ_TOTAL 229376
#define YSTRIDE 264   // floats; 128 rows x 264 x 4B = 135168 B (aliases B/A stages)

__device__ __forceinline__ void q_issue(char* smem, const float* X,
                                        const __nv_bfloat16* Uhi,
                                        const __nv_bfloat16* Ulo,
                                        int stage, int c, int row0,
                                        int n_atoms, int t) {
    const int k0 = c * 64;
#pragma unroll
    for (int p = 0; p < 4; p++) {
        int g = t + p * 512;
        int row = g >> 4, q16 = g & 15;
        uint32_t dst = QAF(stage) + (uint32_t)(row * 256 + q16 * 16);
        if (row0 + row < n_atoms) {
            cpa16(smem_u32(smem) + dst,
                  &X[(size_t)(row0 + row) * D_FEAT + k0 + q16 * 4]);
        } else {
            *(uint4*)(smem + dst) = make_uint4(0, 0, 0, 0);
        }
    }
#pragma unroll
    for (int p = 0; p < 4; p++) {
        int g = t + p * 512;
        int row = g >> 3, kq = g & 7;
        if (row >= c * 64) {
            uint32_t so = sw_off((uint32_t)(row * 128 + kq * 16));
            size_t src = (size_t)row * D_FEAT + k0 + kq * 8;
            cpa16(smem_u32(smem) + QB(stage) + so, &Uhi[src]);
            cpa16(smem_u32(smem) + QBL(stage) + so, &Ulo[src]);
        }
    }
}

__global__ void __launch_bounds__(512, 1)
k_quad_mma(const float* __restrict__ X, const int* __restrict__ rowseg,
           float* __restrict__ out, int n_atoms) {
    extern __shared__ char smem[];
    const uint32_t sbase = smem_u32(smem);
    const int t    = threadIdx.x;
    const int lane = t & 31;
    const int w    = t >> 5;
    const int wr   = w & 3;
    const int wc   = w >> 2;
    const int row0 = blockIdx.x * QM;

    // acc[mt][i*2+n2]: stripe i covers cols i*64 + wc*16 .. +16
    float acc[2][8][4];
#pragma unroll
    for (int mt = 0; mt < 2; mt++)
#pragma unroll
        for (int nt = 0; nt < 8; nt++)
#pragma unroll
            for (int e = 0; e < 4; e++) acc[mt][nt][e] = 0.f;

    q_issue(smem, X, g_Uhi, g_Ulo, 0, 0, row0, n_atoms, t);
    CP_COMMIT();

#pragma unroll
    for (int c = 0; c < 4; c++) {
        const int st = c & 1;
        CP_WAIT(0);
        __syncthreads();
        if (c < 3) {
            q_issue(smem, X, g_Uhi, g_Ulo, 1 - st, c + 1, row0, n_atoms, t);
            CP_COMMIT();
        }
        // convert A fp32 stage -> bf16 hi/lo (SW128)
#pragma unroll
        for (int p = 0; p < 4; p++) {
            int g = t + p * 512;
            int row = g >> 4, kq = g & 15;
            float4 v = *(const float4*)(smem + QAF(st) + row * 256 + kq * 16);
            uint32_t h0, l0, h1, l1;
            bsplit(v.x, v.y, h0, l0);
            bsplit(v.z, v.w, h1, l1);
            uint32_t so = sw_off((uint32_t)(row * 128 + kq * 8));
            *(uint2*)(smem + QAH + so) = make_uint2(h0, h1);
            *(uint2*)(smem + QAL + so) = make_uint2(l0, l1);
        }
        __syncthreads();

#pragma unroll
        for (int ks = 0; ks < 4; ks++) {
            const int kk = ks * 16;
            uint32_t Ah[2][4], Al[2][4];
            ldsmA(sbase + QAH, wr * 32 + 0,  kk, lane, Ah[0]);
            ldsmA(sbase + QAH, wr * 32 + 16, kk, lane, Ah[1]);
            ldsmA(sbase + QAL, wr * 32 + 0,  kk, lane, Al[0]);
            ldsmA(sbase + QAL, wr * 32 + 16, kk, lane, Al[1]);
#pragma unroll
            for (int i = 0; i < 4; i++) {
                if (i < c) continue;              // compile-time (unrolled)
                uint32_t Bh[4], Bl[4];
                ldsmB(sbase + QB(st),  i * 64 + wc * 16, kk, lane, Bh);
                ldsmB(sbase + QBL(st), i * 64 + wc * 16, kk, lane, Bl);
#pragma unroll
                for (int mt = 0; mt < 2; mt++)
#pragma unroll
                    for (int n2 = 0; n2 < 2; n2++)
                        mma16816(acc[mt][i * 2 + n2], Ah[mt], Bh + n2 * 2);
#pragma unroll
                for (int mt = 0; mt < 2; mt++)
#pragma unroll
                    for (int n2 = 0; n2 < 2; n2++)
                        mma16816(acc[mt][i * 2 + n2], Ah[mt], Bl + n2 * 2);
#pragma unroll
                for (int mt = 0; mt < 2; mt++)
#pragma unroll
                    for (int n2 = 0; n2 < 2; n2++)
                        mma16816(acc[mt][i * 2 + n2], Al[mt], Bh + n2 * 2);
            }
        }
    }

    // ---- epilogue v2: fragments -> SMEM Y, then coalesced X dot ----
    __syncthreads();          // all MMA/ldmatrix done; B buffers now dead
    float* Ysm = (float*)smem;
#pragma unroll
    for (int mt = 0; mt < 2; mt++)
#pragma unroll
        for (int i = 0; i < 4; i++)
#pragma unroll
            for (int n2 = 0; n2 < 2; n2++)
#pragma unroll
                for (int half = 0; half < 2; half++) {
                    int row = wr * 32 + mt * 16 + (lane >> 2) + half * 8;
                    int col = i * 64 + wc * 16 + n2 * 8 + (lane & 3) * 2;
                    float2 v = make_float2(acc[mt][i * 2 + n2][half * 2 + 0],
                                           acc[mt][i * 2 + n2][half * 2 + 1]);
                    *(float2*)&Ysm[row * YSTRIDE + col] = v;
                }
    __syncthreads();

    // pass 2: warp w owns rows w*8 .. w*8+8; coalesced X read
#pragma unroll
    for (int i = 0; i < 8; i++) {
        int rloc = w * 8 + i;
        int rg   = row0 + rloc;
        float q = 0.f, nn = 0.f;
        if (rg < n_atoms) {
#pragma unroll
            for (int k = 0; k < 4; k++) {
                float2 xv = *(const float2*)&X[(size_t)rg * D_FEAT + k * 64 + lane * 2];
                float2 yv = *(const float2*)&Ysm[rloc * YSTRIDE + k * 64 + lane * 2];
                q  = fmaf(xv.x, yv.x, q);
                q  = fmaf(xv.y, yv.y, q);
                nn = fmaf(xv.x, xv.x, nn);
                nn = fmaf(xv.y, xv.y, nn);
            }
        }
#pragma unroll
        for (int off = 16; off > 0; off >>= 1) {
            q  += __shfl_xor_sync(0xFFFFFFFFu, q, off);
            nn += __shfl_xor_sync(0xFFFFFFFFu, nn, off);
        }
        if (lane == 0 && rg < n_atoms)
            atomicAdd(&out[rowseg[rg]], 2.0f * q / nn);
    }
}

// ---- launch --------------------------------------------------------------------
extern "C" void kernel_launch(void* const* d_in, const int* in_sizes, int n_in,
                              void* d_out, int out_size) {
    const float* X      = (const float*)d_in[0];
    const float* S      = (const float*)d_in[1];
    const float* W      = (const float*)d_in[2];
    const int*   rowseg = (const int*)d_in[3];
    const int*   colseg = (const int*)d_in[4];
    float* out = (float*)d_out;

    int n_atoms   = in_sizes[0] / D_FEAT;
    int n_support = in_sizes[1] / D_FEAT;
    int n_struct  = out_size;

    cudaFuncSetAttribute(k_quad_mma, cudaFuncAttributeMaxDynamicSharedMemorySize,
                         SMQ_TOTAL);
    cudaFuncSetAttribute(k_build_mma, cudaFuncAttributeMaxDynamicSharedMemorySize,
                         SMB_TOTAL);

    k_build_mma<<<3 * NSPL, 512, SMB_TOTAL>>>(S, W, colseg, n_support);
    k_convM<<<D_FEAT * D_FEAT / 256, 256>>>(out, n_struct);
    int gQ = (n_atoms + QM - 1) / QM;
    k_quad_mma<<<gQ, 512, SMQ_TOTAL>>>(X, rowseg, out, n_atoms);
}